// round 11
// baseline (speedup 1.0000x reference)
#include <cuda_runtime.h>
#include <cuda_bf16.h>
#include <math.h>
#include <stdint.h>

// Problem constants
#define Bb 2
#define Ss 4096
#define INs 2048
#define STATEs 2048
#define OUTs 2048
#define Hh 16
#define Dd 128
#define CHs 6144               // 3*STATE
#define FACTOR_ 0.0214373219f  // 1/sqrt(2048+128)

#define N_SCAN_CTAS 32
#define N_WORKERS   116
#define CHUNK_S     128        // s-steps per completion chunk
#define N_CHUNKS    (Ss / CHUNK_S)          // 32
#define TILES_PER_CHUNK (2 * (CHs / 128))   // 96
#define N_TILES     (N_CHUNKS * TILES_PER_CHUNK)  // 3072  (GEMM1)
#define N_TILES2    ((Bb * Ss / 128) * (OUTs / 128))  // 1024 (GEMM2)

// ---------------- scratch (device globals: allocation-free) ----------------
__device__ float g_z [(size_t)Bb * Ss * CHs];    // after GEMM1+tanh
__device__ int   g_done [N_CHUNKS];              // z chunk counters (96 each)
__device__ int   g_ydone[Bb * N_CHUNKS];         // y chunk counters (16 each)

// bf16 hi/lo split buffers
__device__ __nv_bfloat16 g_xhi[(size_t)Bb * Ss * INs];
__device__ __nv_bfloat16 g_xlo[(size_t)Bb * Ss * INs];
__device__ __nv_bfloat16 g_whi[(size_t)CHs * INs];
__device__ __nv_bfloat16 g_wlo[(size_t)CHs * INs];
__device__ __nv_bfloat16 g_yhi[(size_t)Bb * Ss * STATEs];
__device__ __nv_bfloat16 g_ylo[(size_t)Bb * Ss * STATEs];
__device__ __nv_bfloat16 g_ohi[(size_t)OUTs * STATEs];
__device__ __nv_bfloat16 g_olo[(size_t)OUTs * STATEs];

// ---------------- math helpers ----------------
__device__ __forceinline__ float fast_tanh(float x) {
    float e = __expf(2.0f * x);
    return 1.0f - 2.0f / (e + 1.0f);
}
__device__ __forceinline__ float fast_sigmoid(float x) {
    return 1.0f / (1.0f + __expf(-x));
}

__device__ __forceinline__ uint32_t smem_to_u32(const void* p) {
    uint32_t a;
    asm("{ .reg .u64 t; cvta.to.shared.u64 t, %1; cvt.u32.u64 %0, t; }"
        : "=r"(a) : "l"(p));
    return a;
}
__device__ __forceinline__ void cpa16(uint32_t s, const void* g) {
    asm volatile("cp.async.cg.shared.global [%0], [%1], 16;\n"
                 :: "r"(s), "l"(g) : "memory");
}
__device__ __forceinline__ void cpa_commit() {
    asm volatile("cp.async.commit_group;\n" ::: "memory");
}
template <int N>
__device__ __forceinline__ void cpa_wait() {
    asm volatile("cp.async.wait_group %0;\n" :: "n"(N) : "memory");
}
__device__ __forceinline__ void ldsm_x4(uint32_t* r, uint32_t addr) {
    asm volatile("ldmatrix.sync.aligned.m8n8.x4.shared.b16 {%0,%1,%2,%3}, [%4];"
                 : "=r"(r[0]), "=r"(r[1]), "=r"(r[2]), "=r"(r[3]) : "r"(addr));
}
__device__ __forceinline__ void mma_bf16(float* c, const uint32_t* a, const uint32_t* b) {
    asm volatile(
        "mma.sync.aligned.m16n8k16.row.col.f32.bf16.bf16.f32 "
        "{%0,%1,%2,%3}, {%4,%5,%6,%7}, {%8,%9}, {%0,%1,%2,%3};"
        : "+f"(c[0]), "+f"(c[1]), "+f"(c[2]), "+f"(c[3])
        : "r"(a[0]), "r"(a[1]), "r"(a[2]), "r"(a[3]), "r"(b[0]), "r"(b[1]));
}

// packed f32x2 helpers (sm_100+ PTX, not 'a'-gated)
__device__ __forceinline__ unsigned long long pack2(float x, float y) {
    unsigned long long r;
    asm("mov.b64 %0, {%1, %2};" : "=l"(r) : "f"(x), "f"(y));
    return r;
}
#define FMA2(acc, a, b) \
    asm("fma.rn.f32x2 %0, %1, %2, %0;" : "+l"(acc) : "l"(a), "l"(b))
#define ADD2(r, a, b) \
    asm("add.rn.f32x2 %0, %1, %2;" : "=l"(r) : "l"(a), "l"(b))

// ---------------- split fp32 -> bf16 hi + lo --------------------------------
__global__ void __launch_bounds__(256)
split_bf16(const float* __restrict__ in, __nv_bfloat16* __restrict__ hi,
           __nv_bfloat16* __restrict__ lo, size_t n)
{
    size_t i = ((size_t)blockIdx.x * 256 + threadIdx.x) * 4;
    if (i >= n) return;
    float4 v = *(const float4*)(in + i);
    __nv_bfloat16 h0 = __float2bfloat16(v.x);
    __nv_bfloat16 h1 = __float2bfloat16(v.y);
    __nv_bfloat16 h2 = __float2bfloat16(v.z);
    __nv_bfloat16 h3 = __float2bfloat16(v.w);
    __nv_bfloat16 l0 = __float2bfloat16(v.x - __bfloat162float(h0));
    __nv_bfloat16 l1 = __float2bfloat16(v.y - __bfloat162float(h1));
    __nv_bfloat16 l2 = __float2bfloat16(v.z - __bfloat162float(h2));
    __nv_bfloat16 l3 = __float2bfloat16(v.w - __bfloat162float(h3));
    __nv_bfloat162* H = (__nv_bfloat162*)(hi + i);
    __nv_bfloat162* L = (__nv_bfloat162*)(lo + i);
    H[0] = __nv_bfloat162(h0, h1); H[1] = __nv_bfloat162(h2, h3);
    L[0] = __nv_bfloat162(l0, l1); L[1] = __nv_bfloat162(l2, l3);
}

__global__ void zero_done() {
    int i = threadIdx.x;
    if (i < N_CHUNKS) g_done[i] = 0;
    if (i < Bb * N_CHUNKS) g_ydone[i] = 0;
}

// ---------------- GEMM tile geometry ----------------------------------------
#define LDPB 144                     // padded row length in bytes (64 bf16 + pad)
#define ARR_BYTES (128 * LDPB)       // 18432 (128 rows)
#define STG_BYTES (4 * ARR_BYTES)    // 73728 (Ahi,Alo,Bhi,Blo per stage)
#define FUSED_SMEM (2 * STG_BYTES)   // 147456 (2-stage)

// ============================================================================
// FUSED: CTAs [0,32) = GRU scan (inline conv, publishes y chunks);
// CTAs [32,148) = workers: 3072 GEMM1 tiles (publish z chunks), then
// 1024 GEMM2 tiles gated on y chunks. One persistent launch.
// ============================================================================
__global__ void __launch_bounds__(256, 1)
fused_all(const __nv_bfloat16* __restrict__ Ahi, const __nv_bfloat16* __restrict__ Alo,
          const __nv_bfloat16* __restrict__ Bhi, const __nv_bfloat16* __restrict__ Blo,
          const float* __restrict__ bias, float* __restrict__ Z,
          const float* __restrict__ sw,
          const float* __restrict__ cw, const float* __restrict__ cb,
          __nv_bfloat16* __restrict__ yh, __nv_bfloat16* __restrict__ yl,
          const __nv_bfloat16* __restrict__ Ohi, const __nv_bfloat16* __restrict__ Olo,
          float* __restrict__ Out)
{
    extern __shared__ char smem[];
    __shared__ __align__(16) unsigned long long h_pair[128];
    __shared__ __align__(16) unsigned long long rh_pair[128];
    __shared__ unsigned long long pr[4][64], pf[4][64], pc[4][64];

    const int tid = threadIdx.x;

    if (blockIdx.x >= N_SCAN_CTAS) {
        // ================= worker: GEMM1 tiles then GEMM2 tiles =============
        const uint32_t su = smem_to_u32(smem);
        const int wk   = blockIdx.x - N_SCAN_CTAS;
        const int wid  = tid >> 5;
        const int lane = tid & 31;
        const int warp_m = wid >> 2;    // 0..1
        const int warp_n = wid & 3;     // 0..3
        const int K = INs;              // 2048 for both GEMMs
        const int NCH = K >> 6;

        const uint32_t a_lane = (uint32_t)((lane & 15) * LDPB + (lane >> 4) * 16)
                              + (uint32_t)(warp_m * 64) * LDPB;
        const int g = lane >> 3;
        const uint32_t b_lane = (uint32_t)((((g >> 1) * 8) + (lane & 7)) * LDPB + (g & 1) * 16)
                              + (uint32_t)(warp_n * 32) * LDPB;

        const __nv_bfloat16 *tA0, *tA1, *tB0, *tB1;
        int bm, bn, chunk = 0;
        bool g1;

        for (int t = wk; t < N_TILES + N_TILES2; t += N_WORKERS) {
            if (t < N_TILES) {
                g1 = true;
                chunk = t / TILES_PER_CHUNK;
                const int sub  = t % TILES_PER_CHUNK;
                const int bsub = sub / (CHs / 128);
                const int ncol = sub % (CHs / 128);
                bm = bsub * Ss + chunk * CHUNK_S;
                bn = ncol << 7;
                tA0 = Ahi; tA1 = Alo; tB0 = Bhi; tB1 = Blo;
            } else {
                g1 = false;
                const int tt   = t - N_TILES;
                const int c    = tt >> 5;         // chunk-major ordering
                const int sub  = tt & 31;
                const int bsub = sub >> 4;
                const int ncol = sub & 15;
                bm = bsub * Ss + c * CHUNK_S;
                bn = ncol << 7;
                tA0 = yh; tA1 = yl; tB0 = Ohi; tB1 = Olo;
                if (tid == 0) {
                    volatile int* p = &g_ydone[bsub * N_CHUNKS + c];
                    while (*p < Hh) { __nanosleep(128); }
                }
                __syncthreads();
                __threadfence();
            }

            auto load_chunk = [&](int ci, int st) {
                uint32_t sb = su + (uint32_t)st * STG_BYTES;
                size_t kbase = (size_t)ci * 64;
#pragma unroll
                for (int u = 0; u < 4; u++) {
                    int s   = tid + u * 256;
                    int row = s >> 3;
                    int ks  = s & 7;
                    uint32_t so = (uint32_t)row * LDPB + (uint32_t)ks * 16;
                    size_t gA = (size_t)(bm + row) * K + kbase + ks * 8;
                    size_t gB = (size_t)(bn + row) * K + kbase + ks * 8;
                    cpa16(sb +                 so, tA0 + gA);
                    cpa16(sb + 1 * ARR_BYTES + so, tA1 + gA);
                    cpa16(sb + 2 * ARR_BYTES + so, tB0 + gB);
                    cpa16(sb + 3 * ARR_BYTES + so, tB1 + gB);
                }
                cpa_commit();
            };

            float acc[4][4][4];
#pragma unroll
            for (int i = 0; i < 4; i++)
#pragma unroll
                for (int j = 0; j < 4; j++)
#pragma unroll
                    for (int k = 0; k < 4; k++) acc[i][j][k] = 0.0f;

            load_chunk(0, 0);
            for (int i = 0; i < NCH; i++) {
                __syncthreads();
                if (i + 1 < NCH) load_chunk(i + 1, (i + 1) & 1);
                if (i + 1 < NCH) cpa_wait<1>(); else cpa_wait<0>();
                __syncthreads();

                uint32_t sb  = su + (uint32_t)(i & 1) * STG_BYTES;
                uint32_t ah  = sb + a_lane;
                uint32_t al  = sb + 1 * ARR_BYTES + a_lane;
                uint32_t bh  = sb + 2 * ARR_BYTES + b_lane;
                uint32_t bl  = sb + 3 * ARR_BYTES + b_lane;

#pragma unroll
                for (int ks = 0; ks < 4; ks++) {
                    uint32_t ko = (uint32_t)ks * 32;
                    uint32_t fa_h[4][4], fa_l[4][4];
                    uint32_t fb_h[4][2], fb_l[4][2];
#pragma unroll
                    for (int mi = 0; mi < 4; mi++) {
                        ldsm_x4(fa_h[mi], ah + (uint32_t)(mi * 16) * LDPB + ko);
                        ldsm_x4(fa_l[mi], al + (uint32_t)(mi * 16) * LDPB + ko);
                    }
#pragma unroll
                    for (int p = 0; p < 2; p++) {
                        uint32_t r[4];
                        ldsm_x4(r, bh + (uint32_t)(p * 16) * LDPB + ko);
                        fb_h[p * 2 + 0][0] = r[0]; fb_h[p * 2 + 0][1] = r[1];
                        fb_h[p * 2 + 1][0] = r[2]; fb_h[p * 2 + 1][1] = r[3];
                        ldsm_x4(r, bl + (uint32_t)(p * 16) * LDPB + ko);
                        fb_l[p * 2 + 0][0] = r[0]; fb_l[p * 2 + 0][1] = r[1];
                        fb_l[p * 2 + 1][0] = r[2]; fb_l[p * 2 + 1][1] = r[3];
                    }
#pragma unroll
                    for (int mi = 0; mi < 4; mi++)
#pragma unroll
                        for (int ni = 0; ni < 4; ni++) {
                            mma_bf16(acc[mi][ni], fa_h[mi], fb_h[ni]);
                            mma_bf16(acc[mi][ni], fa_h[mi], fb_l[ni]);
                            mma_bf16(acc[mi][ni], fa_l[mi], fb_h[ni]);
                        }
                }
            }

            const int gid = lane >> 2;
            const int tig = lane & 3;
            if (g1) {
#pragma unroll
                for (int mi = 0; mi < 4; mi++) {
                    int row0 = bm + warp_m * 64 + mi * 16 + gid;
#pragma unroll
                    for (int ni = 0; ni < 4; ni++) {
                        int col = bn + warp_n * 32 + ni * 8 + tig * 2;
                        float b0 = bias[col], b1 = bias[col + 1];
                        float v0 = fast_tanh(acc[mi][ni][0] + b0);
                        float v1 = fast_tanh(acc[mi][ni][1] + b1);
                        float v2 = fast_tanh(acc[mi][ni][2] + b0);
                        float v3 = fast_tanh(acc[mi][ni][3] + b1);
                        *(float2*)(Z + (size_t)row0 * CHs + col)       = make_float2(v0, v1);
                        *(float2*)(Z + (size_t)(row0 + 8) * CHs + col) = make_float2(v2, v3);
                    }
                }
                __threadfence();
                __syncthreads();
                if (tid == 0) atomicAdd(&g_done[chunk], 1);
            } else {
#pragma unroll
                for (int mi = 0; mi < 4; mi++) {
                    int row0 = bm + warp_m * 64 + mi * 16 + gid;
#pragma unroll
                    for (int ni = 0; ni < 4; ni++) {
                        int col = bn + warp_n * 32 + ni * 8 + tig * 2;
                        *(float2*)(Out + (size_t)row0 * OUTs + col)
                            = make_float2(acc[mi][ni][0], acc[mi][ni][1]);
                        *(float2*)(Out + (size_t)(row0 + 8) * OUTs + col)
                            = make_float2(acc[mi][ni][2], acc[mi][ni][3]);
                    }
                }
            }
        }
        return;
    }

    // ================= GRU scan (v3) + inline conv + y publication =========
    const int b   = blockIdx.x >> 4;
    const int hh  = blockIdx.x & 15;
    const int c2  = tid & 63;
    const int q   = tid >> 6;
    const int d0  = q << 5;

    const float* wc_g = sw + (size_t)(hh)      * Dd * Dd;  // cand
    const float* wf_g = sw + (size_t)(16 + hh) * Dd * Dd;  // forget
    const float* wr_g = sw + (size_t)(32 + hh) * Dd * Dd;  // reset

    unsigned long long wc[32], wf[32], wr[32];
#pragma unroll
    for (int j = 0; j < 32; j++) {
        float2 t;
        t = *(const float2*)(wc_g + (size_t)(d0 + j) * 128 + 2 * c2);
        wc[j] = pack2(t.x * FACTOR_, t.y * FACTOR_);
        t = *(const float2*)(wf_g + (size_t)(d0 + j) * 128 + 2 * c2);
        wf[j] = pack2(t.x * FACTOR_, t.y * FACTOR_);
        t = *(const float2*)(wr_g + (size_t)(d0 + j) * 128 + 2 * c2);
        wr[j] = pack2(t.x * FACTOR_, t.y * FACTOR_);
    }
    if (tid < 128) h_pair[tid] = 0ULL;

    const int col = hh * 128 + tid;
    const float* zb = Z + (size_t)b * Ss * CHs;
    __nv_bfloat16* yhb = yh + (size_t)b * Ss * STATEs + col;
    __nv_bfloat16* ylb = yl + (size_t)b * Ss * STATEs + col;
    const float* prf = (const float*)pr;
    const float* pff = (const float*)pf;
    const float* pcf = (const float*)pc;

    float cwi0=0,cwi1=0,cwi2=0,cwi3=0, cwf0=0,cwf1=0,cwf2=0,cwf3=0;
    float cwr0=0,cwr1=0,cwr2=0,cwr3=0, cbi=0, cbf=0, cbr=0;
    if (tid < 128) {
        const float4 wi  = *(const float4*)(cw + (size_t)col * 4);
        const float4 wfv = *(const float4*)(cw + (size_t)(2048 + col) * 4);
        const float4 wrv = *(const float4*)(cw + (size_t)(4096 + col) * 4);
        cwi0=wi.x; cwi1=wi.y; cwi2=wi.z; cwi3=wi.w;
        cwf0=wfv.x; cwf1=wfv.y; cwf2=wfv.z; cwf3=wfv.w;
        cwr0=wrv.x; cwr1=wrv.y; cwr2=wrv.z; cwr3=wrv.w;
        cbi = cb[col]; cbf = cb[2048 + col]; cbr = cb[4096 + col];
    }
    __syncthreads();

    // wait for first z chunk, prime prefetch registers for s=0 and s=1
    {
        volatile int* p = &g_done[0];
        while (*p < TILES_PER_CHUNK) { __nanosleep(128); }
        __threadfence();
    }
    float xi0=0,xi1=0,xi2=0, xf0=0,xf1=0,xf2=0, xr0=0,xr1=0,xr2=0;
    float cur_i=0, cur_f=0, cur_r=0;     // z[s]
    float p1_i=0, p1_f=0, p1_r=0;        // z[s+1]
    if (tid < 128) {
        cur_i = zb[col];        cur_f = zb[2048 + col];        cur_r = zb[4096 + col];
        const float* z1 = zb + CHs;
        p1_i = z1[col];         p1_f = z1[2048 + col];         p1_r = z1[4096 + col];
    }
    float hcur = 0.f;

    for (int s = 0; s < Ss; s++) {
        float zci=0, zcf=0, zcr=0;
        if (tid < 128) {
            zci = (cwi0*xi0 + cwi1*xi1 + cwi2*xi2 + cwi3*cur_i + cbi) * FACTOR_;
            zcf = (cwf0*xf0 + cwf1*xf1 + cwf2*xf2 + cwf3*cur_f + cbf) * FACTOR_;
            zcr = (cwr0*xr0 + cwr1*xr1 + cwr2*xr2 + cwr3*cur_r + cbr) * FACTOR_;
        }

        // gate and prefetch z[s+2] (2-step depth covers worker-loaded latency)
        if ((s + 2) < Ss && (((s + 2) & (CHUNK_S - 1)) == 0)) {
            volatile int* p = &g_done[(s + 2) >> 7];
            while (*p < TILES_PER_CHUNK) { __nanosleep(128); }
            __threadfence();
        }
        float p2_i = 0.f, p2_f = 0.f, p2_r = 0.f;
        if (tid < 128 && s + 2 < Ss) {
            const float* zs = zb + (size_t)(s + 2) * CHs;
            p2_i = zs[col];
            p2_f = zs[2048 + col];
            p2_r = zs[4096 + col];
        }

        // phase 1: partial r/f over d in [d0, d0+32), 2 accums per gate
        unsigned long long ar0 = 0ULL, ar1 = 0ULL, af0 = 0ULL, af1 = 0ULL;
        {
            const ulonglong2* hp = (const ulonglong2*)(h_pair + d0);
#pragma unroll
            for (int j = 0; j < 16; j++) {
                ulonglong2 hv = hp[j];
                FMA2(ar0, hv.x, wr[2 * j]);
                FMA2(af0, hv.x, wf[2 * j]);
                FMA2(ar1, hv.y, wr[2 * j + 1]);
                FMA2(af1, hv.y, wf[2 * j + 1]);
            }
        }
        unsigned long long art, aft;
        ADD2(art, ar0, ar1);
        ADD2(aft, af0, af1);
        pr[q][c2] = art;
        pf[q][c2] = aft;
        __syncthreads();

        // boundary 1: r sigmoid + rh publish; f's sigmoid DEFERRED to phase 2
        float fs = 0.f;
        if (tid < 128) {
            float rs = zcr + prf[tid] + prf[128 + tid] + prf[256 + tid] + prf[384 + tid];
            fs = zcf + pff[tid] + pff[128 + tid] + pff[256 + tid] + pff[384 + tid];
            float r  = fast_sigmoid(rs);
            float rh = r * hcur;
            rh_pair[tid] = pack2(rh, rh);
        }
        __syncthreads();

        // phase 2: partial cand on (r*h); f sigmoid interleaves with FMA2s
        unsigned long long ac0 = 0ULL, ac1 = 0ULL;
        float ff = 0.f;
        if (tid < 128) ff = fast_sigmoid(fs);   // independent of the loop below
        {
            const ulonglong2* rp = (const ulonglong2*)(rh_pair + d0);
#pragma unroll
            for (int j = 0; j < 16; j++) {
                ulonglong2 hv = rp[j];
                FMA2(ac0, hv.x, wc[2 * j]);
                FMA2(ac1, hv.y, wc[2 * j + 1]);
            }
        }
        unsigned long long act;
        ADD2(act, ac0, ac1);
        pc[q][c2] = act;
        __syncthreads();

        if (tid < 128) {
            float cs = zci + pcf[tid] + pcf[128 + tid] + pcf[256 + tid] + pcf[384 + tid];
            float cd = fast_tanh(cs);
            float hn = fmaf(ff, hcur - cd, cd);
            hcur = hn;
            h_pair[tid] = pack2(hn, hn);
            __nv_bfloat16 bh = __float2bfloat16(hn);
            yhb[(size_t)s * STATEs] = bh;
            ylb[(size_t)s * STATEs] = __float2bfloat16(hn - __bfloat162float(bh));
            // shift conv windows + prefetch pipeline
            xi0 = xi1; xi1 = xi2; xi2 = cur_i; cur_i = p1_i; p1_i = p2_i;
            xf0 = xf1; xf1 = xf2; xf2 = cur_f; cur_f = p1_f; p1_f = p2_f;
            xr0 = xr1; xr1 = xr2; xr2 = cur_r; cur_r = p1_r; p1_r = p2_r;
        }
        __syncthreads();

        if ((s & (CHUNK_S - 1)) == (CHUNK_S - 1)) {
            __threadfence();
            __syncthreads();
            if (tid == 0) atomicAdd(&g_ydone[b * N_CHUNKS + (s >> 7)], 1);
        }
    }
}

// ---------------- launch ----------------
extern "C" void kernel_launch(void* const* d_in, const int* in_sizes, int n_in,
                              void* d_out, int out_size)
{
    const float* x    = (const float*)d_in[0];
    const float* w_in = (const float*)d_in[1];
    const float* b_in = (const float*)d_in[2];
    const float* cw   = (const float*)d_in[3];
    const float* cb   = (const float*)d_in[4];
    const float* swt  = (const float*)d_in[5];
    const float* wout = (const float*)d_in[6];
    float* out = (float*)d_out;

    float* zp;
    cudaGetSymbolAddress((void**)&zp, g_z);
    __nv_bfloat16 *xh, *xl, *wh, *wl, *yh, *yl, *oh, *ol;
    cudaGetSymbolAddress((void**)&xh, g_xhi);
    cudaGetSymbolAddress((void**)&xl, g_xlo);
    cudaGetSymbolAddress((void**)&wh, g_whi);
    cudaGetSymbolAddress((void**)&wl, g_wlo);
    cudaGetSymbolAddress((void**)&yh, g_yhi);
    cudaGetSymbolAddress((void**)&yl, g_ylo);
    cudaGetSymbolAddress((void**)&oh, g_ohi);
    cudaGetSymbolAddress((void**)&ol, g_olo);

    // splits + flag reset
    {
        size_t nx = (size_t)Bb * Ss * INs;
        split_bf16<<<(int)(nx / 1024), 256>>>(x, xh, xl, nx);
        size_t nw = (size_t)CHs * INs;
        split_bf16<<<(int)(nw / 1024), 256>>>(w_in, wh, wl, nw);
        size_t no = (size_t)OUTs * STATEs;
        split_bf16<<<(int)(no / 1024), 256>>>(wout, oh, ol, no);
        zero_done<<<1, 128>>>();
    }

    // fused GEMM1 + conv + scan + GEMM2
    {
        cudaFuncSetAttribute(fused_all,
                             cudaFuncAttributeMaxDynamicSharedMemorySize,
                             FUSED_SMEM);
        fused_all<<<N_SCAN_CTAS + N_WORKERS, 256, FUSED_SMEM>>>(
            xh, xl, wh, wl, b_in, zp, swt, cw, cb, yh, yl, oh, ol, out);
    }
}

// round 12
// speedup vs baseline: 1.0116x; 1.0116x over previous
#include <cuda_runtime.h>
#include <cuda_bf16.h>
#include <math.h>
#include <stdint.h>

// Problem constants
#define Bb 2
#define Ss 4096
#define INs 2048
#define STATEs 2048
#define OUTs 2048
#define Hh 16
#define Dd 128
#define CHs 6144               // 3*STATE
#define FACTOR_ 0.0214373219f  // 1/sqrt(2048+128)

#define N_SCAN_CTAS 32
#define N_WORKERS   116
#define CHUNK_S     128        // s-steps per completion chunk
#define N_CHUNKS    (Ss / CHUNK_S)          // 32
#define TILES_PER_CHUNK (2 * (CHs / 128))   // 96
#define N_TILES     (N_CHUNKS * TILES_PER_CHUNK)  // 3072  (GEMM1)
#define N_TILES2    ((Bb * Ss / 128) * (OUTs / 128))  // 1024 (GEMM2)

// ---------------- scratch (device globals: allocation-free) ----------------
__device__ float g_z [(size_t)Bb * Ss * CHs];    // after GEMM1+tanh
__device__ int   g_done [N_CHUNKS];              // z chunk counters (96 each)
__device__ int   g_ydone[Bb * N_CHUNKS];         // y chunk counters (16 each)

// bf16 hi/lo split buffers
__device__ __nv_bfloat16 g_xhi[(size_t)Bb * Ss * INs];
__device__ __nv_bfloat16 g_xlo[(size_t)Bb * Ss * INs];
__device__ __nv_bfloat16 g_whi[(size_t)CHs * INs];
__device__ __nv_bfloat16 g_wlo[(size_t)CHs * INs];
__device__ __nv_bfloat16 g_yhi[(size_t)Bb * Ss * STATEs];
__device__ __nv_bfloat16 g_ylo[(size_t)Bb * Ss * STATEs];
__device__ __nv_bfloat16 g_ohi[(size_t)OUTs * STATEs];
__device__ __nv_bfloat16 g_olo[(size_t)OUTs * STATEs];

// ---------------- math helpers ----------------
__device__ __forceinline__ float fast_tanh(float x) {
    float e = __expf(2.0f * x);
    return 1.0f - 2.0f / (e + 1.0f);
}
__device__ __forceinline__ float fast_sigmoid(float x) {
    return 1.0f / (1.0f + __expf(-x));
}

__device__ __forceinline__ uint32_t smem_to_u32(const void* p) {
    uint32_t a;
    asm("{ .reg .u64 t; cvta.to.shared.u64 t, %1; cvt.u32.u64 %0, t; }"
        : "=r"(a) : "l"(p));
    return a;
}
__device__ __forceinline__ void cpa16(uint32_t s, const void* g) {
    asm volatile("cp.async.cg.shared.global [%0], [%1], 16;\n"
                 :: "r"(s), "l"(g) : "memory");
}
__device__ __forceinline__ void cpa_commit() {
    asm volatile("cp.async.commit_group;\n" ::: "memory");
}
template <int N>
__device__ __forceinline__ void cpa_wait() {
    asm volatile("cp.async.wait_group %0;\n" :: "n"(N) : "memory");
}
__device__ __forceinline__ void ldsm_x4(uint32_t* r, uint32_t addr) {
    asm volatile("ldmatrix.sync.aligned.m8n8.x4.shared.b16 {%0,%1,%2,%3}, [%4];"
                 : "=r"(r[0]), "=r"(r[1]), "=r"(r[2]), "=r"(r[3]) : "r"(addr));
}
__device__ __forceinline__ void mma_bf16(float* c, const uint32_t* a, const uint32_t* b) {
    asm volatile(
        "mma.sync.aligned.m16n8k16.row.col.f32.bf16.bf16.f32 "
        "{%0,%1,%2,%3}, {%4,%5,%6,%7}, {%8,%9}, {%0,%1,%2,%3};"
        : "+f"(c[0]), "+f"(c[1]), "+f"(c[2]), "+f"(c[3])
        : "r"(a[0]), "r"(a[1]), "r"(a[2]), "r"(a[3]), "r"(b[0]), "r"(b[1]));
}

// packed f32x2 helpers (sm_100+ PTX, not 'a'-gated)
__device__ __forceinline__ unsigned long long pack2(float x, float y) {
    unsigned long long r;
    asm("mov.b64 %0, {%1, %2};" : "=l"(r) : "f"(x), "f"(y));
    return r;
}
#define FMA2(acc, a, b) \
    asm("fma.rn.f32x2 %0, %1, %2, %0;" : "+l"(acc) : "l"(a), "l"(b))
#define ADD2(r, a, b) \
    asm("add.rn.f32x2 %0, %1, %2;" : "=l"(r) : "l"(a), "l"(b))

// ---------------- split fp32 -> bf16 hi + lo --------------------------------
__global__ void __launch_bounds__(256)
split_bf16(const float* __restrict__ in, __nv_bfloat16* __restrict__ hi,
           __nv_bfloat16* __restrict__ lo, size_t n)
{
    size_t i = ((size_t)blockIdx.x * 256 + threadIdx.x) * 4;
    if (i >= n) return;
    float4 v = *(const float4*)(in + i);
    __nv_bfloat16 h0 = __float2bfloat16(v.x);
    __nv_bfloat16 h1 = __float2bfloat16(v.y);
    __nv_bfloat16 h2 = __float2bfloat16(v.z);
    __nv_bfloat16 h3 = __float2bfloat16(v.w);
    __nv_bfloat16 l0 = __float2bfloat16(v.x - __bfloat162float(h0));
    __nv_bfloat16 l1 = __float2bfloat16(v.y - __bfloat162float(h1));
    __nv_bfloat16 l2 = __float2bfloat16(v.z - __bfloat162float(h2));
    __nv_bfloat16 l3 = __float2bfloat16(v.w - __bfloat162float(h3));
    __nv_bfloat162* H = (__nv_bfloat162*)(hi + i);
    __nv_bfloat162* L = (__nv_bfloat162*)(lo + i);
    H[0] = __nv_bfloat162(h0, h1); H[1] = __nv_bfloat162(h2, h3);
    L[0] = __nv_bfloat162(l0, l1); L[1] = __nv_bfloat162(l2, l3);
}

__global__ void zero_done() {
    int i = threadIdx.x;
    if (i < N_CHUNKS) g_done[i] = 0;
    if (i < Bb * N_CHUNKS) g_ydone[i] = 0;
}

// ---------------- GEMM tile geometry ----------------------------------------
#define LDPB 144                     // padded row length in bytes (64 bf16 + pad)
#define ARR_BYTES (128 * LDPB)       // 18432 (128 rows)
#define STG_BYTES (4 * ARR_BYTES)    // 73728 (Ahi,Alo,Bhi,Blo per stage)
#define FUSED_SMEM (2 * STG_BYTES)   // 147456 (2-stage)

// ============================================================================
// FUSED: CTAs [0,32) = GRU scan (inline conv, publishes y chunks);
// CTAs [32,148) = workers: 3072 GEMM1 tiles (publish z chunks), then
// 1024 GEMM2 tiles gated on y chunks. One persistent launch.
// ============================================================================
__global__ void __launch_bounds__(256, 1)
fused_all(const __nv_bfloat16* __restrict__ Ahi, const __nv_bfloat16* __restrict__ Alo,
          const __nv_bfloat16* __restrict__ Bhi, const __nv_bfloat16* __restrict__ Blo,
          const float* __restrict__ bias, float* __restrict__ Z,
          const float* __restrict__ sw,
          const float* __restrict__ cw, const float* __restrict__ cb,
          __nv_bfloat16* __restrict__ yh, __nv_bfloat16* __restrict__ yl,
          const __nv_bfloat16* __restrict__ Ohi, const __nv_bfloat16* __restrict__ Olo,
          float* __restrict__ Out)
{
    extern __shared__ char smem[];
    __shared__ __align__(16) unsigned long long h_pair[128];
    __shared__ __align__(16) unsigned long long rh_pair[128];
    __shared__ unsigned long long pr[4][64], pf[4][64], pc[4][64];

    const int tid = threadIdx.x;

    if (blockIdx.x >= N_SCAN_CTAS) {
        // ================= worker: GEMM1 tiles then GEMM2 tiles =============
        const uint32_t su = smem_to_u32(smem);
        const int wk   = blockIdx.x - N_SCAN_CTAS;
        const int wid  = tid >> 5;
        const int lane = tid & 31;
        const int warp_m = wid >> 2;    // 0..1
        const int warp_n = wid & 3;     // 0..3
        const int K = INs;              // 2048 for both GEMMs
        const int NCH = K >> 6;

        const uint32_t a_lane = (uint32_t)((lane & 15) * LDPB + (lane >> 4) * 16)
                              + (uint32_t)(warp_m * 64) * LDPB;
        const int g = lane >> 3;
        const uint32_t b_lane = (uint32_t)((((g >> 1) * 8) + (lane & 7)) * LDPB + (g & 1) * 16)
                              + (uint32_t)(warp_n * 32) * LDPB;

        const __nv_bfloat16 *tA0, *tA1, *tB0, *tB1;
        int bm, bn, chunk = 0;
        bool g1;

        for (int t = wk; t < N_TILES + N_TILES2; t += N_WORKERS) {
            if (t < N_TILES) {
                g1 = true;
                chunk = t / TILES_PER_CHUNK;
                const int sub  = t % TILES_PER_CHUNK;
                const int bsub = sub / (CHs / 128);
                const int ncol = sub % (CHs / 128);
                bm = bsub * Ss + chunk * CHUNK_S;
                bn = ncol << 7;
                tA0 = Ahi; tA1 = Alo; tB0 = Bhi; tB1 = Blo;
            } else {
                g1 = false;
                const int tt   = t - N_TILES;
                const int c    = tt >> 5;         // chunk-major ordering
                const int sub  = tt & 31;
                const int bsub = sub >> 4;
                const int ncol = sub & 15;
                bm = bsub * Ss + c * CHUNK_S;
                bn = ncol << 7;
                tA0 = yh; tA1 = yl; tB0 = Ohi; tB1 = Olo;
                if (tid == 0) {
                    volatile int* p = &g_ydone[bsub * N_CHUNKS + c];
                    while (*p < Hh) { __nanosleep(128); }
                }
                __syncthreads();
                __threadfence();
            }

            auto load_chunk = [&](int ci, int st) {
                uint32_t sb = su + (uint32_t)st * STG_BYTES;
                size_t kbase = (size_t)ci * 64;
#pragma unroll
                for (int u = 0; u < 4; u++) {
                    int s   = tid + u * 256;
                    int row = s >> 3;
                    int ks  = s & 7;
                    uint32_t so = (uint32_t)row * LDPB + (uint32_t)ks * 16;
                    size_t gA = (size_t)(bm + row) * K + kbase + ks * 8;
                    size_t gB = (size_t)(bn + row) * K + kbase + ks * 8;
                    cpa16(sb +                 so, tA0 + gA);
                    cpa16(sb + 1 * ARR_BYTES + so, tA1 + gA);
                    cpa16(sb + 2 * ARR_BYTES + so, tB0 + gB);
                    cpa16(sb + 3 * ARR_BYTES + so, tB1 + gB);
                }
                cpa_commit();
            };

            float acc[4][4][4];
#pragma unroll
            for (int i = 0; i < 4; i++)
#pragma unroll
                for (int j = 0; j < 4; j++)
#pragma unroll
                    for (int k = 0; k < 4; k++) acc[i][j][k] = 0.0f;

            load_chunk(0, 0);
            for (int i = 0; i < NCH; i++) {
                __syncthreads();
                if (i + 1 < NCH) load_chunk(i + 1, (i + 1) & 1);
                if (i + 1 < NCH) cpa_wait<1>(); else cpa_wait<0>();
                __syncthreads();

                uint32_t sb  = su + (uint32_t)(i & 1) * STG_BYTES;
                uint32_t ah  = sb + a_lane;
                uint32_t al  = sb + 1 * ARR_BYTES + a_lane;
                uint32_t bh  = sb + 2 * ARR_BYTES + b_lane;
                uint32_t bl  = sb + 3 * ARR_BYTES + b_lane;

#pragma unroll
                for (int ks = 0; ks < 4; ks++) {
                    uint32_t ko = (uint32_t)ks * 32;
                    uint32_t fa_h[4][4], fa_l[4][4];
                    uint32_t fb_h[4][2], fb_l[4][2];
#pragma unroll
                    for (int mi = 0; mi < 4; mi++) {
                        ldsm_x4(fa_h[mi], ah + (uint32_t)(mi * 16) * LDPB + ko);
                        ldsm_x4(fa_l[mi], al + (uint32_t)(mi * 16) * LDPB + ko);
                    }
#pragma unroll
                    for (int p = 0; p < 2; p++) {
                        uint32_t r[4];
                        ldsm_x4(r, bh + (uint32_t)(p * 16) * LDPB + ko);
                        fb_h[p * 2 + 0][0] = r[0]; fb_h[p * 2 + 0][1] = r[1];
                        fb_h[p * 2 + 1][0] = r[2]; fb_h[p * 2 + 1][1] = r[3];
                        ldsm_x4(r, bl + (uint32_t)(p * 16) * LDPB + ko);
                        fb_l[p * 2 + 0][0] = r[0]; fb_l[p * 2 + 0][1] = r[1];
                        fb_l[p * 2 + 1][0] = r[2]; fb_l[p * 2 + 1][1] = r[3];
                    }
#pragma unroll
                    for (int mi = 0; mi < 4; mi++)
#pragma unroll
                        for (int ni = 0; ni < 4; ni++) {
                            mma_bf16(acc[mi][ni], fa_h[mi], fb_h[ni]);
                            mma_bf16(acc[mi][ni], fa_h[mi], fb_l[ni]);
                            mma_bf16(acc[mi][ni], fa_l[mi], fb_h[ni]);
                        }
                }
            }

            const int gid = lane >> 2;
            const int tig = lane & 3;
            if (g1) {
#pragma unroll
                for (int mi = 0; mi < 4; mi++) {
                    int row0 = bm + warp_m * 64 + mi * 16 + gid;
#pragma unroll
                    for (int ni = 0; ni < 4; ni++) {
                        int col = bn + warp_n * 32 + ni * 8 + tig * 2;
                        float b0 = bias[col], b1 = bias[col + 1];
                        float v0 = fast_tanh(acc[mi][ni][0] + b0);
                        float v1 = fast_tanh(acc[mi][ni][1] + b1);
                        float v2 = fast_tanh(acc[mi][ni][2] + b0);
                        float v3 = fast_tanh(acc[mi][ni][3] + b1);
                        *(float2*)(Z + (size_t)row0 * CHs + col)       = make_float2(v0, v1);
                        *(float2*)(Z + (size_t)(row0 + 8) * CHs + col) = make_float2(v2, v3);
                    }
                }
                __threadfence();
                __syncthreads();
                if (tid == 0) atomicAdd(&g_done[chunk], 1);
            } else {
#pragma unroll
                for (int mi = 0; mi < 4; mi++) {
                    int row0 = bm + warp_m * 64 + mi * 16 + gid;
#pragma unroll
                    for (int ni = 0; ni < 4; ni++) {
                        int col = bn + warp_n * 32 + ni * 8 + tig * 2;
                        *(float2*)(Out + (size_t)row0 * OUTs + col)
                            = make_float2(acc[mi][ni][0], acc[mi][ni][1]);
                        *(float2*)(Out + (size_t)(row0 + 8) * OUTs + col)
                            = make_float2(acc[mi][ni][2], acc[mi][ni][3]);
                    }
                }
            }
        }
        return;
    }

    // ================= GRU scan (R10 base) + 4-accum FMA2 chains ===========
    const int b   = blockIdx.x >> 4;
    const int hh  = blockIdx.x & 15;
    const int c2  = tid & 63;
    const int q   = tid >> 6;
    const int d0  = q << 5;

    const float* wc_g = sw + (size_t)(hh)      * Dd * Dd;  // cand
    const float* wf_g = sw + (size_t)(16 + hh) * Dd * Dd;  // forget
    const float* wr_g = sw + (size_t)(32 + hh) * Dd * Dd;  // reset

    unsigned long long wc[32], wf[32], wr[32];
#pragma unroll
    for (int j = 0; j < 32; j++) {
        float2 t;
        t = *(const float2*)(wc_g + (size_t)(d0 + j) * 128 + 2 * c2);
        wc[j] = pack2(t.x * FACTOR_, t.y * FACTOR_);
        t = *(const float2*)(wf_g + (size_t)(d0 + j) * 128 + 2 * c2);
        wf[j] = pack2(t.x * FACTOR_, t.y * FACTOR_);
        t = *(const float2*)(wr_g + (size_t)(d0 + j) * 128 + 2 * c2);
        wr[j] = pack2(t.x * FACTOR_, t.y * FACTOR_);
    }
    if (tid < 128) h_pair[tid] = 0ULL;

    const int col = hh * 128 + tid;
    const float* zb = Z + (size_t)b * Ss * CHs;
    __nv_bfloat16* yhb = yh + (size_t)b * Ss * STATEs + col;
    __nv_bfloat16* ylb = yl + (size_t)b * Ss * STATEs + col;
    const float* prf = (const float*)pr;
    const float* pff = (const float*)pf;
    const float* pcf = (const float*)pc;

    float cwi0=0,cwi1=0,cwi2=0,cwi3=0, cwf0=0,cwf1=0,cwf2=0,cwf3=0;
    float cwr0=0,cwr1=0,cwr2=0,cwr3=0, cbi=0, cbf=0, cbr=0;
    if (tid < 128) {
        const float4 wi  = *(const float4*)(cw + (size_t)col * 4);
        const float4 wfv = *(const float4*)(cw + (size_t)(2048 + col) * 4);
        const float4 wrv = *(const float4*)(cw + (size_t)(4096 + col) * 4);
        cwi0=wi.x; cwi1=wi.y; cwi2=wi.z; cwi3=wi.w;
        cwf0=wfv.x; cwf1=wfv.y; cwf2=wfv.z; cwf3=wfv.w;
        cwr0=wrv.x; cwr1=wrv.y; cwr2=wrv.z; cwr3=wrv.w;
        cbi = cb[col]; cbf = cb[2048 + col]; cbr = cb[4096 + col];
    }
    __syncthreads();

    {
        volatile int* p = &g_done[0];
        while (*p < TILES_PER_CHUNK) { __nanosleep(128); }
        __threadfence();
    }
    float xi0=0,xi1=0,xi2=0, xf0=0,xf1=0,xf2=0, xr0=0,xr1=0,xr2=0;
    float cur_i=0, cur_f=0, cur_r=0;
    if (tid < 128) {
        cur_i = zb[col];
        cur_f = zb[2048 + col];
        cur_r = zb[4096 + col];
    }
    float hcur = 0.f;

    for (int s = 0; s < Ss; s++) {
        float zci=0, zcf=0, zcr=0;
        if (tid < 128) {
            zci = (cwi0*xi0 + cwi1*xi1 + cwi2*xi2 + cwi3*cur_i + cbi) * FACTOR_;
            zcf = (cwf0*xf0 + cwf1*xf1 + cwf2*xf2 + cwf3*cur_f + cbf) * FACTOR_;
            zcr = (cwr0*xr0 + cwr1*xr1 + cwr2*xr2 + cwr3*cur_r + cbr) * FACTOR_;
        }

        if ((s & (CHUNK_S - 1)) == (CHUNK_S - 1) && s + 1 < Ss) {
            volatile int* p = &g_done[(s + 1) >> 7];
            while (*p < TILES_PER_CHUNK) { __nanosleep(128); }
            __threadfence();
        }

        float ni = 0.f, nf = 0.f, nr = 0.f;
        if (tid < 128 && s + 1 < Ss) {
            const float* zs = zb + (size_t)(s + 1) * CHs;
            ni = zs[col];
            nf = zs[2048 + col];
            nr = zs[4096 + col];
        }

        // phase 1: partial r/f over d in [d0, d0+32), 4 accums per gate
        unsigned long long ar[4] = {0ULL, 0ULL, 0ULL, 0ULL};
        unsigned long long af[4] = {0ULL, 0ULL, 0ULL, 0ULL};
        {
            const ulonglong2* hp = (const ulonglong2*)(h_pair + d0);
#pragma unroll
            for (int j = 0; j < 16; j++) {
                ulonglong2 hv = hp[j];
                FMA2(ar[(2 * j) & 3],     hv.x, wr[2 * j]);
                FMA2(af[(2 * j) & 3],     hv.x, wf[2 * j]);
                FMA2(ar[(2 * j + 1) & 3], hv.y, wr[2 * j + 1]);
                FMA2(af[(2 * j + 1) & 3], hv.y, wf[2 * j + 1]);
            }
        }
        unsigned long long art, aft, t0, t1;
        ADD2(t0, ar[0], ar[1]);
        ADD2(t1, ar[2], ar[3]);
        ADD2(art, t0, t1);
        ADD2(t0, af[0], af[1]);
        ADD2(t1, af[2], af[3]);
        ADD2(aft, t0, t1);
        pr[q][c2] = art;
        pf[q][c2] = aft;
        __syncthreads();

        float ff = 0.f;
        if (tid < 128) {
            float rs = zcr + prf[tid] + prf[128 + tid] + prf[256 + tid] + prf[384 + tid];
            float fs = zcf + pff[tid] + pff[128 + tid] + pff[256 + tid] + pff[384 + tid];
            float r  = fast_sigmoid(rs);
            ff = fast_sigmoid(fs);
            float rh = r * hcur;
            rh_pair[tid] = pack2(rh, rh);
        }
        __syncthreads();

        // phase 2: partial cand on (r*h), 4 accums
        unsigned long long ac[4] = {0ULL, 0ULL, 0ULL, 0ULL};
        {
            const ulonglong2* rp = (const ulonglong2*)(rh_pair + d0);
#pragma unroll
            for (int j = 0; j < 16; j++) {
                ulonglong2 hv = rp[j];
                FMA2(ac[(2 * j) & 3],     hv.x, wc[2 * j]);
                FMA2(ac[(2 * j + 1) & 3], hv.y, wc[2 * j + 1]);
            }
        }
        unsigned long long act;
        ADD2(t0, ac[0], ac[1]);
        ADD2(t1, ac[2], ac[3]);
        ADD2(act, t0, t1);
        pc[q][c2] = act;
        __syncthreads();

        if (tid < 128) {
            float cs = zci + pcf[tid] + pcf[128 + tid] + pcf[256 + tid] + pcf[384 + tid];
            float cd = fast_tanh(cs);
            float hn = fmaf(ff, hcur - cd, cd);
            hcur = hn;
            h_pair[tid] = pack2(hn, hn);
            __nv_bfloat16 bh = __float2bfloat16(hn);
            yhb[(size_t)s * STATEs] = bh;
            ylb[(size_t)s * STATEs] = __float2bfloat16(hn - __bfloat162float(bh));
            xi0 = xi1; xi1 = xi2; xi2 = cur_i; cur_i = ni;
            xf0 = xf1; xf1 = xf2; xf2 = cur_f; cur_f = nf;
            xr0 = xr1; xr1 = xr2; xr2 = cur_r; cur_r = nr;
        }
        __syncthreads();

        if ((s & (CHUNK_S - 1)) == (CHUNK_S - 1)) {
            __threadfence();
            __syncthreads();
            if (tid == 0) atomicAdd(&g_ydone[b * N_CHUNKS + (s >> 7)], 1);
        }
    }
}

// ---------------- launch ----------------
extern "C" void kernel_launch(void* const* d_in, const int* in_sizes, int n_in,
                              void* d_out, int out_size)
{
    const float* x    = (const float*)d_in[0];
    const float* w_in = (const float*)d_in[1];
    const float* b_in = (const float*)d_in[2];
    const float* cw   = (const float*)d_in[3];
    const float* cb   = (const float*)d_in[4];
    const float* swt  = (const float*)d_in[5];
    const float* wout = (const float*)d_in[6];
    float* out = (float*)d_out;

    float* zp;
    cudaGetSymbolAddress((void**)&zp, g_z);
    __nv_bfloat16 *xh, *xl, *wh, *wl, *yh, *yl, *oh, *ol;
    cudaGetSymbolAddress((void**)&xh, g_xhi);
    cudaGetSymbolAddress((void**)&xl, g_xlo);
    cudaGetSymbolAddress((void**)&wh, g_whi);
    cudaGetSymbolAddress((void**)&wl, g_wlo);
    cudaGetSymbolAddress((void**)&yh, g_yhi);
    cudaGetSymbolAddress((void**)&yl, g_ylo);
    cudaGetSymbolAddress((void**)&oh, g_ohi);
    cudaGetSymbolAddress((void**)&ol, g_olo);

    // splits + flag reset
    {
        size_t nx = (size_t)Bb * Ss * INs;
        split_bf16<<<(int)(nx / 1024), 256>>>(x, xh, xl, nx);
        size_t nw = (size_t)CHs * INs;
        split_bf16<<<(int)(nw / 1024), 256>>>(w_in, wh, wl, nw);
        size_t no = (size_t)OUTs * STATEs;
        split_bf16<<<(int)(no / 1024), 256>>>(wout, oh, ol, no);
        zero_done<<<1, 128>>>();
    }

    // fused GEMM1 + conv + scan + GEMM2
    {
        cudaFuncSetAttribute(fused_all,
                             cudaFuncAttributeMaxDynamicSharedMemorySize,
                             FUSED_SMEM);
        fused_all<<<N_SCAN_CTAS + N_WORKERS, 256, FUSED_SMEM>>>(
            xh, xl, wh, wl, b_in, zp, swt, cw, cb, yh, yl, oh, ol, out);
    }
}

// round 13
// speedup vs baseline: 1.0553x; 1.0432x over previous
#include <cuda_runtime.h>
#include <cuda_bf16.h>
#include <math.h>
#include <stdint.h>

// Problem constants
#define Bb 2
#define Ss 4096
#define INs 2048
#define STATEs 2048
#define OUTs 2048
#define Hh 16
#define Dd 128
#define CHs 6144               // 3*STATE
#define FACTOR_ 0.0214373219f  // 1/sqrt(2048+128)

#define N_SCAN_CTAS 32
#define N_WORKERS   116
#define CHUNK_S     128        // s-steps per completion chunk
#define N_CHUNKS    (Ss / CHUNK_S)          // 32
#define TILES_PER_CHUNK (2 * (CHs / 128))   // 96
#define N_TILES     (N_CHUNKS * TILES_PER_CHUNK)  // 3072  (GEMM1)
#define N_TILES2    ((Bb * Ss / 128) * (OUTs / 128))  // 1024 (GEMM2)

// ---------------- scratch (device globals: allocation-free) ----------------
__device__ float g_z [(size_t)Bb * Ss * CHs];    // after GEMM1+tanh
__device__ int   g_done [N_CHUNKS];              // z chunk counters (96 each)
__device__ int   g_ydone[Bb * N_CHUNKS];         // y chunk counters (16 each)

// bf16 hi/lo split buffers
__device__ __nv_bfloat16 g_xhi[(size_t)Bb * Ss * INs];
__device__ __nv_bfloat16 g_xlo[(size_t)Bb * Ss * INs];
__device__ __nv_bfloat16 g_whi[(size_t)CHs * INs];
__device__ __nv_bfloat16 g_wlo[(size_t)CHs * INs];
__device__ __nv_bfloat16 g_yhi[(size_t)Bb * Ss * STATEs];
__device__ __nv_bfloat16 g_ylo[(size_t)Bb * Ss * STATEs];
__device__ __nv_bfloat16 g_ohi[(size_t)OUTs * STATEs];
__device__ __nv_bfloat16 g_olo[(size_t)OUTs * STATEs];

// ---------------- math helpers ----------------
__device__ __forceinline__ float fast_tanh(float x) {
    float e = __expf(2.0f * x);
    return 1.0f - 2.0f / (e + 1.0f);
}
__device__ __forceinline__ float fast_sigmoid(float x) {
    return 1.0f / (1.0f + __expf(-x));
}

__device__ __forceinline__ uint32_t smem_to_u32(const void* p) {
    uint32_t a;
    asm("{ .reg .u64 t; cvta.to.shared.u64 t, %1; cvt.u32.u64 %0, t; }"
        : "=r"(a) : "l"(p));
    return a;
}
__device__ __forceinline__ void cpa16(uint32_t s, const void* g) {
    asm volatile("cp.async.cg.shared.global [%0], [%1], 16;\n"
                 :: "r"(s), "l"(g) : "memory");
}
__device__ __forceinline__ void cpa4(uint32_t s, const void* g) {
    asm volatile("cp.async.ca.shared.global [%0], [%1], 4;\n"
                 :: "r"(s), "l"(g) : "memory");
}
__device__ __forceinline__ void cpa_commit() {
    asm volatile("cp.async.commit_group;\n" ::: "memory");
}
template <int N>
__device__ __forceinline__ void cpa_wait() {
    asm volatile("cp.async.wait_group %0;\n" :: "n"(N) : "memory");
}
__device__ __forceinline__ void ldsm_x4(uint32_t* r, uint32_t addr) {
    asm volatile("ldmatrix.sync.aligned.m8n8.x4.shared.b16 {%0,%1,%2,%3}, [%4];"
                 : "=r"(r[0]), "=r"(r[1]), "=r"(r[2]), "=r"(r[3]) : "r"(addr));
}
__device__ __forceinline__ void mma_bf16(float* c, const uint32_t* a, const uint32_t* b) {
    asm volatile(
        "mma.sync.aligned.m16n8k16.row.col.f32.bf16.bf16.f32 "
        "{%0,%1,%2,%3}, {%4,%5,%6,%7}, {%8,%9}, {%0,%1,%2,%3};"
        : "+f"(c[0]), "+f"(c[1]), "+f"(c[2]), "+f"(c[3])
        : "r"(a[0]), "r"(a[1]), "r"(a[2]), "r"(a[3]), "r"(b[0]), "r"(b[1]));
}

// packed f32x2 helpers (sm_100+ PTX, not 'a'-gated)
__device__ __forceinline__ unsigned long long pack2(float x, float y) {
    unsigned long long r;
    asm("mov.b64 %0, {%1, %2};" : "=l"(r) : "f"(x), "f"(y));
    return r;
}
#define FMA2(acc, a, b) \
    asm("fma.rn.f32x2 %0, %1, %2, %0;" : "+l"(acc) : "l"(a), "l"(b))
#define ADD2(r, a, b) \
    asm("add.rn.f32x2 %0, %1, %2;" : "=l"(r) : "l"(a), "l"(b))

// ---------------- split fp32 -> bf16 hi + lo --------------------------------
__global__ void __launch_bounds__(256)
split_bf16(const float* __restrict__ in, __nv_bfloat16* __restrict__ hi,
           __nv_bfloat16* __restrict__ lo, size_t n)
{
    size_t i = ((size_t)blockIdx.x * 256 + threadIdx.x) * 4;
    if (i >= n) return;
    float4 v = *(const float4*)(in + i);
    __nv_bfloat16 h0 = __float2bfloat16(v.x);
    __nv_bfloat16 h1 = __float2bfloat16(v.y);
    __nv_bfloat16 h2 = __float2bfloat16(v.z);
    __nv_bfloat16 h3 = __float2bfloat16(v.w);
    __nv_bfloat16 l0 = __float2bfloat16(v.x - __bfloat162float(h0));
    __nv_bfloat16 l1 = __float2bfloat16(v.y - __bfloat162float(h1));
    __nv_bfloat16 l2 = __float2bfloat16(v.z - __bfloat162float(h2));
    __nv_bfloat16 l3 = __float2bfloat16(v.w - __bfloat162float(h3));
    __nv_bfloat162* H = (__nv_bfloat162*)(hi + i);
    __nv_bfloat162* L = (__nv_bfloat162*)(lo + i);
    H[0] = __nv_bfloat162(h0, h1); H[1] = __nv_bfloat162(h2, h3);
    L[0] = __nv_bfloat162(l0, l1); L[1] = __nv_bfloat162(l2, l3);
}

__global__ void zero_done() {
    int i = threadIdx.x;
    if (i < N_CHUNKS) g_done[i] = 0;
    if (i < Bb * N_CHUNKS) g_ydone[i] = 0;
}

// ---------------- GEMM tile geometry ----------------------------------------
#define LDPB 144                     // padded row length in bytes (64 bf16 + pad)
#define ARR_BYTES (128 * LDPB)       // 18432 (128 rows)
#define STG_BYTES (4 * ARR_BYTES)    // 73728 (Ahi,Alo,Bhi,Blo per stage)
#define FUSED_SMEM (2 * STG_BYTES)   // 147456 (2-stage)

// ============================================================================
// FUSED: CTAs [0,32) = GRU scan (inline conv, publishes y chunks);
// CTAs [32,148) = workers: 3072 GEMM1 tiles (publish z chunks), then
// 1024 GEMM2 tiles gated on y chunks. One persistent launch.
// ============================================================================
__global__ void __launch_bounds__(256, 1)
fused_all(const __nv_bfloat16* __restrict__ Ahi, const __nv_bfloat16* __restrict__ Alo,
          const __nv_bfloat16* __restrict__ Bhi, const __nv_bfloat16* __restrict__ Blo,
          const float* __restrict__ bias, float* __restrict__ Z,
          const float* __restrict__ sw,
          const float* __restrict__ cw, const float* __restrict__ cb,
          __nv_bfloat16* __restrict__ yh, __nv_bfloat16* __restrict__ yl,
          const __nv_bfloat16* __restrict__ Ohi, const __nv_bfloat16* __restrict__ Olo,
          float* __restrict__ Out)
{
    extern __shared__ char smem[];
    __shared__ __align__(16) unsigned long long h_pair[128];
    __shared__ __align__(16) unsigned long long rh_pair[128];
    __shared__ unsigned long long pr[4][64], pf[4][64], pc[4][64];
    __shared__ __align__(16) float zstage[3][384];   // z rows: [i|f|r] x 128

    const int tid = threadIdx.x;

    if (blockIdx.x >= N_SCAN_CTAS) {
        // ================= worker: GEMM1 tiles then GEMM2 tiles =============
        const uint32_t su = smem_to_u32(smem);
        const int wk   = blockIdx.x - N_SCAN_CTAS;
        const int wid  = tid >> 5;
        const int lane = tid & 31;
        const int warp_m = wid >> 2;    // 0..1
        const int warp_n = wid & 3;     // 0..3
        const int K = INs;              // 2048 for both GEMMs
        const int NCH = K >> 6;

        const uint32_t a_lane = (uint32_t)((lane & 15) * LDPB + (lane >> 4) * 16)
                              + (uint32_t)(warp_m * 64) * LDPB;
        const int g = lane >> 3;
        const uint32_t b_lane = (uint32_t)((((g >> 1) * 8) + (lane & 7)) * LDPB + (g & 1) * 16)
                              + (uint32_t)(warp_n * 32) * LDPB;

        const __nv_bfloat16 *tA0, *tA1, *tB0, *tB1;
        int bm, bn, chunk = 0;
        bool g1;

        for (int t = wk; t < N_TILES + N_TILES2; t += N_WORKERS) {
            if (t < N_TILES) {
                g1 = true;
                chunk = t / TILES_PER_CHUNK;
                const int sub  = t % TILES_PER_CHUNK;
                const int bsub = sub / (CHs / 128);
                const int ncol = sub % (CHs / 128);
                bm = bsub * Ss + chunk * CHUNK_S;
                bn = ncol << 7;
                tA0 = Ahi; tA1 = Alo; tB0 = Bhi; tB1 = Blo;
            } else {
                g1 = false;
                const int tt   = t - N_TILES;
                const int c    = tt >> 5;         // chunk-major ordering
                const int sub  = tt & 31;
                const int bsub = sub >> 4;
                const int ncol = sub & 15;
                bm = bsub * Ss + c * CHUNK_S;
                bn = ncol << 7;
                tA0 = yh; tA1 = yl; tB0 = Ohi; tB1 = Olo;
                if (tid == 0) {
                    volatile int* p = &g_ydone[bsub * N_CHUNKS + c];
                    while (*p < Hh) { __nanosleep(128); }
                }
                __syncthreads();
                __threadfence();
            }

            auto load_chunk = [&](int ci, int st) {
                uint32_t sb = su + (uint32_t)st * STG_BYTES;
                size_t kbase = (size_t)ci * 64;
#pragma unroll
                for (int u = 0; u < 4; u++) {
                    int s   = tid + u * 256;
                    int row = s >> 3;
                    int ks  = s & 7;
                    uint32_t so = (uint32_t)row * LDPB + (uint32_t)ks * 16;
                    size_t gA = (size_t)(bm + row) * K + kbase + ks * 8;
                    size_t gB = (size_t)(bn + row) * K + kbase + ks * 8;
                    cpa16(sb +                 so, tA0 + gA);
                    cpa16(sb + 1 * ARR_BYTES + so, tA1 + gA);
                    cpa16(sb + 2 * ARR_BYTES + so, tB0 + gB);
                    cpa16(sb + 3 * ARR_BYTES + so, tB1 + gB);
                }
                cpa_commit();
            };

            float acc[4][4][4];
#pragma unroll
            for (int i = 0; i < 4; i++)
#pragma unroll
                for (int j = 0; j < 4; j++)
#pragma unroll
                    for (int k = 0; k < 4; k++) acc[i][j][k] = 0.0f;

            load_chunk(0, 0);
            for (int i = 0; i < NCH; i++) {
                __syncthreads();
                if (i + 1 < NCH) load_chunk(i + 1, (i + 1) & 1);
                if (i + 1 < NCH) cpa_wait<1>(); else cpa_wait<0>();
                __syncthreads();

                uint32_t sb  = su + (uint32_t)(i & 1) * STG_BYTES;
                uint32_t ah  = sb + a_lane;
                uint32_t al  = sb + 1 * ARR_BYTES + a_lane;
                uint32_t bh  = sb + 2 * ARR_BYTES + b_lane;
                uint32_t bl  = sb + 3 * ARR_BYTES + b_lane;

#pragma unroll
                for (int ks = 0; ks < 4; ks++) {
                    uint32_t ko = (uint32_t)ks * 32;
                    uint32_t fa_h[4][4], fa_l[4][4];
                    uint32_t fb_h[4][2], fb_l[4][2];
#pragma unroll
                    for (int mi = 0; mi < 4; mi++) {
                        ldsm_x4(fa_h[mi], ah + (uint32_t)(mi * 16) * LDPB + ko);
                        ldsm_x4(fa_l[mi], al + (uint32_t)(mi * 16) * LDPB + ko);
                    }
#pragma unroll
                    for (int p = 0; p < 2; p++) {
                        uint32_t r[4];
                        ldsm_x4(r, bh + (uint32_t)(p * 16) * LDPB + ko);
                        fb_h[p * 2 + 0][0] = r[0]; fb_h[p * 2 + 0][1] = r[1];
                        fb_h[p * 2 + 1][0] = r[2]; fb_h[p * 2 + 1][1] = r[3];
                        ldsm_x4(r, bl + (uint32_t)(p * 16) * LDPB + ko);
                        fb_l[p * 2 + 0][0] = r[0]; fb_l[p * 2 + 0][1] = r[1];
                        fb_l[p * 2 + 1][0] = r[2]; fb_l[p * 2 + 1][1] = r[3];
                    }
#pragma unroll
                    for (int mi = 0; mi < 4; mi++)
#pragma unroll
                        for (int ni = 0; ni < 4; ni++) {
                            mma_bf16(acc[mi][ni], fa_h[mi], fb_h[ni]);
                            mma_bf16(acc[mi][ni], fa_h[mi], fb_l[ni]);
                            mma_bf16(acc[mi][ni], fa_l[mi], fb_h[ni]);
                        }
                }
            }

            const int gid = lane >> 2;
            const int tig = lane & 3;
            if (g1) {
#pragma unroll
                for (int mi = 0; mi < 4; mi++) {
                    int row0 = bm + warp_m * 64 + mi * 16 + gid;
#pragma unroll
                    for (int ni = 0; ni < 4; ni++) {
                        int col = bn + warp_n * 32 + ni * 8 + tig * 2;
                        float b0 = bias[col], b1 = bias[col + 1];
                        float v0 = fast_tanh(acc[mi][ni][0] + b0);
                        float v1 = fast_tanh(acc[mi][ni][1] + b1);
                        float v2 = fast_tanh(acc[mi][ni][2] + b0);
                        float v3 = fast_tanh(acc[mi][ni][3] + b1);
                        *(float2*)(Z + (size_t)row0 * CHs + col)       = make_float2(v0, v1);
                        *(float2*)(Z + (size_t)(row0 + 8) * CHs + col) = make_float2(v2, v3);
                    }
                }
                __threadfence();
                __syncthreads();
                if (tid == 0) atomicAdd(&g_done[chunk], 1);
            } else {
#pragma unroll
                for (int mi = 0; mi < 4; mi++) {
                    int row0 = bm + warp_m * 64 + mi * 16 + gid;
#pragma unroll
                    for (int ni = 0; ni < 4; ni++) {
                        int col = bn + warp_n * 32 + ni * 8 + tig * 2;
                        *(float2*)(Out + (size_t)row0 * OUTs + col)
                            = make_float2(acc[mi][ni][0], acc[mi][ni][1]);
                        *(float2*)(Out + (size_t)(row0 + 8) * OUTs + col)
                            = make_float2(acc[mi][ni][2], acc[mi][ni][3]);
                    }
                }
            }
        }
        return;
    }

    // ================= GRU scan (exact R10 math) + cp.async z staging ======
    const int b   = blockIdx.x >> 4;
    const int hh  = blockIdx.x & 15;
    const int c2  = tid & 63;
    const int q   = tid >> 6;
    const int d0  = q << 5;

    const float* wc_g = sw + (size_t)(hh)      * Dd * Dd;  // cand
    const float* wf_g = sw + (size_t)(16 + hh) * Dd * Dd;  // forget
    const float* wr_g = sw + (size_t)(32 + hh) * Dd * Dd;  // reset

    unsigned long long wc[32], wf[32], wr[32];
#pragma unroll
    for (int j = 0; j < 32; j++) {
        float2 t;
        t = *(const float2*)(wc_g + (size_t)(d0 + j) * 128 + 2 * c2);
        wc[j] = pack2(t.x * FACTOR_, t.y * FACTOR_);
        t = *(const float2*)(wf_g + (size_t)(d0 + j) * 128 + 2 * c2);
        wf[j] = pack2(t.x * FACTOR_, t.y * FACTOR_);
        t = *(const float2*)(wr_g + (size_t)(d0 + j) * 128 + 2 * c2);
        wr[j] = pack2(t.x * FACTOR_, t.y * FACTOR_);
    }
    if (tid < 128) h_pair[tid] = 0ULL;

    const int col = hh * 128 + tid;
    const float* zb = Z + (size_t)b * Ss * CHs;
    __nv_bfloat16* yhb = yh + (size_t)b * Ss * STATEs + col;
    __nv_bfloat16* ylb = yl + (size_t)b * Ss * STATEs + col;
    const float* prf = (const float*)pr;
    const float* pff = (const float*)pf;
    const float* pcf = (const float*)pc;

    float cwi0=0,cwi1=0,cwi2=0,cwi3=0, cwf0=0,cwf1=0,cwf2=0,cwf3=0;
    float cwr0=0,cwr1=0,cwr2=0,cwr3=0, cbi=0, cbf=0, cbr=0;
    if (tid < 128) {
        const float4 wi  = *(const float4*)(cw + (size_t)col * 4);
        const float4 wfv = *(const float4*)(cw + (size_t)(2048 + col) * 4);
        const float4 wrv = *(const float4*)(cw + (size_t)(4096 + col) * 4);
        cwi0=wi.x; cwi1=wi.y; cwi2=wi.z; cwi3=wi.w;
        cwf0=wfv.x; cwf1=wfv.y; cwf2=wfv.z; cwf3=wfv.w;
        cwr0=wrv.x; cwr1=wrv.y; cwr2=wrv.z; cwr3=wrv.w;
        cbi = cb[col]; cbf = cb[2048 + col]; cbr = cb[4096 + col];
    }
    __syncthreads();

    // wait for first z chunk, prime cp.async staging for s=0 and s=1
    {
        volatile int* p = &g_done[0];
        while (*p < TILES_PER_CHUNK) { __nanosleep(128); }
        __threadfence();
    }
    if (tid < 128) {
        cpa4(smem_to_u32(&zstage[0][tid]),       zb + col);
        cpa4(smem_to_u32(&zstage[0][128 + tid]), zb + 2048 + col);
        cpa4(smem_to_u32(&zstage[0][256 + tid]), zb + 4096 + col);
        cpa_commit();
        const float* z1 = zb + CHs;
        cpa4(smem_to_u32(&zstage[1][tid]),       z1 + col);
        cpa4(smem_to_u32(&zstage[1][128 + tid]), z1 + 2048 + col);
        cpa4(smem_to_u32(&zstage[1][256 + tid]), z1 + 4096 + col);
        cpa_commit();
    }

    float xi0=0,xi1=0,xi2=0, xf0=0,xf1=0,xf2=0, xr0=0,xr1=0,xr2=0;
    float hcur = 0.f;

    for (int s = 0; s < Ss; s++) {
        // retire group s (self-produced data: no barrier needed), read z[s]
        float cur_i=0, cur_f=0, cur_r=0;
        float zci=0, zcf=0, zcr=0;
        if (tid < 128) {
            cpa_wait<1>();
            const float* zs = &zstage[s % 3][0];
            cur_i = zs[tid]; cur_f = zs[128 + tid]; cur_r = zs[256 + tid];
            zci = (cwi0*xi0 + cwi1*xi1 + cwi2*xi2 + cwi3*cur_i + cbi) * FACTOR_;
            zcf = (cwf0*xf0 + cwf1*xf1 + cwf2*xf2 + cwf3*cur_f + cbf) * FACTOR_;
            zcr = (cwr0*xr0 + cwr1*xr1 + cwr2*xr2 + cwr3*cur_r + cbr) * FACTOR_;
        }

        // gate + issue prefetch of z[s+2] (depth 2, no register payload)
        if ((s + 2) < Ss) {
            if ((((s + 2) & (CHUNK_S - 1)) == 0)) {
                volatile int* p = &g_done[(s + 2) >> 7];
                while (*p < TILES_PER_CHUNK) { __nanosleep(128); }
                __threadfence();
            }
            if (tid < 128) {
                const float* zg = zb + (size_t)(s + 2) * CHs;
                float* dst = &zstage[(s + 2) % 3][0];
                cpa4(smem_to_u32(dst + tid),       zg + col);
                cpa4(smem_to_u32(dst + 128 + tid), zg + 2048 + col);
                cpa4(smem_to_u32(dst + 256 + tid), zg + 4096 + col);
                cpa_commit();
            }
        }

        // phase 1: partial r/f over d in [d0, d0+32), 2 accums per gate (R10)
        unsigned long long ar0 = 0ULL, ar1 = 0ULL, af0 = 0ULL, af1 = 0ULL;
        {
            const ulonglong2* hp = (const ulonglong2*)(h_pair + d0);
#pragma unroll
            for (int j = 0; j < 16; j++) {
                ulonglong2 hv = hp[j];
                FMA2(ar0, hv.x, wr[2 * j]);
                FMA2(af0, hv.x, wf[2 * j]);
                FMA2(ar1, hv.y, wr[2 * j + 1]);
                FMA2(af1, hv.y, wf[2 * j + 1]);
            }
        }
        unsigned long long art, aft;
        ADD2(art, ar0, ar1);
        ADD2(aft, af0, af1);
        pr[q][c2] = art;
        pf[q][c2] = aft;
        __syncthreads();

        float ff = 0.f;
        if (tid < 128) {
            float rs = zcr + prf[tid] + prf[128 + tid] + prf[256 + tid] + prf[384 + tid];
            float fs = zcf + pff[tid] + pff[128 + tid] + pff[256 + tid] + pff[384 + tid];
            float r  = fast_sigmoid(rs);
            ff = fast_sigmoid(fs);
            float rh = r * hcur;
            rh_pair[tid] = pack2(rh, rh);
        }
        __syncthreads();

        // phase 2: partial cand on (r*h), 2 accums (R10)
        unsigned long long ac0 = 0ULL, ac1 = 0ULL;
        {
            const ulonglong2* rp = (const ulonglong2*)(rh_pair + d0);
#pragma unroll
            for (int j = 0; j < 16; j++) {
                ulonglong2 hv = rp[j];
                FMA2(ac0, hv.x, wc[2 * j]);
                FMA2(ac1, hv.y, wc[2 * j + 1]);
            }
        }
        unsigned long long act;
        ADD2(act, ac0, ac1);
        pc[q][c2] = act;
        __syncthreads();

        if (tid < 128) {
            float cs = zci + pcf[tid] + pcf[128 + tid] + pcf[256 + tid] + pcf[384 + tid];
            float cd = fast_tanh(cs);
            float hn = fmaf(ff, hcur - cd, cd);
            hcur = hn;
            h_pair[tid] = pack2(hn, hn);
            __nv_bfloat16 bh = __float2bfloat16(hn);
            yhb[(size_t)s * STATEs] = bh;
            ylb[(size_t)s * STATEs] = __float2bfloat16(hn - __bfloat162float(bh));
            // shift conv window (cur read from smem this step)
            xi0 = xi1; xi1 = xi2; xi2 = cur_i;
            xf0 = xf1; xf1 = xf2; xf2 = cur_f;
            xr0 = xr1; xr1 = xr2; xr2 = cur_r;
        }
        __syncthreads();

        if ((s & (CHUNK_S - 1)) == (CHUNK_S - 1)) {
            __threadfence();
            __syncthreads();
            if (tid == 0) atomicAdd(&g_ydone[b * N_CHUNKS + (s >> 7)], 1);
        }
    }
}

// ---------------- launch ----------------
extern "C" void kernel_launch(void* const* d_in, const int* in_sizes, int n_in,
                              void* d_out, int out_size)
{
    const float* x    = (const float*)d_in[0];
    const float* w_in = (const float*)d_in[1];
    const float* b_in = (const float*)d_in[2];
    const float* cw   = (const float*)d_in[3];
    const float* cb   = (const float*)d_in[4];
    const float* swt  = (const float*)d_in[5];
    const float* wout = (const float*)d_in[6];
    float* out = (float*)d_out;

    float* zp;
    cudaGetSymbolAddress((void**)&zp, g_z);
    __nv_bfloat16 *xh, *xl, *wh, *wl, *yh, *yl, *oh, *ol;
    cudaGetSymbolAddress((void**)&xh, g_xhi);
    cudaGetSymbolAddress((void**)&xl, g_xlo);
    cudaGetSymbolAddress((void**)&wh, g_whi);
    cudaGetSymbolAddress((void**)&wl, g_wlo);
    cudaGetSymbolAddress((void**)&yh, g_yhi);
    cudaGetSymbolAddress((void**)&yl, g_ylo);
    cudaGetSymbolAddress((void**)&oh, g_ohi);
    cudaGetSymbolAddress((void**)&ol, g_olo);

    // splits + flag reset
    {
        size_t nx = (size_t)Bb * Ss * INs;
        split_bf16<<<(int)(nx / 1024), 256>>>(x, xh, xl, nx);
        size_t nw = (size_t)CHs * INs;
        split_bf16<<<(int)(nw / 1024), 256>>>(w_in, wh, wl, nw);
        size_t no = (size_t)OUTs * STATEs;
        split_bf16<<<(int)(no / 1024), 256>>>(wout, oh, ol, no);
        zero_done<<<1, 128>>>();
    }

    // fused GEMM1 + conv + scan + GEMM2
    {
        cudaFuncSetAttribute(fused_all,
                             cudaFuncAttributeMaxDynamicSharedMemorySize,
                             FUSED_SMEM);
        fused_all<<<N_SCAN_CTAS + N_WORKERS, 256, FUSED_SMEM>>>(
            xh, xl, wh, wl, b_in, zp, swt, cw, cb, yh, yl, oh, ol, out);
    }
}

// round 14
// speedup vs baseline: 1.1401x; 1.0803x over previous
#include <cuda_runtime.h>
#include <cuda_bf16.h>
#include <math.h>
#include <stdint.h>

// Problem constants
#define Bb 2
#define Ss 4096
#define INs 2048
#define STATEs 2048
#define OUTs 2048
#define Hh 16
#define Dd 128
#define CHs 6144               // 3*STATE
#define FACTOR_ 0.0214373219f  // 1/sqrt(2048+128)

#define N_SCAN_CTAS 32
#define N_WORKERS   116
#define CHUNK_S     128        // s-steps per completion chunk
#define N_CHUNKS    (Ss / CHUNK_S)          // 32
#define TILES_PER_CHUNK (2 * (CHs / 128))   // 96
#define N_TILES     (N_CHUNKS * TILES_PER_CHUNK)  // 3072  (GEMM1)
#define N_TILES2    ((Bb * Ss / 128) * (OUTs / 128))  // 1024 (GEMM2)

// ---------------- scratch (device globals: allocation-free) ----------------
__device__ float g_z [(size_t)Bb * Ss * CHs];    // after GEMM1+tanh
__device__ int   g_done [N_CHUNKS];              // z chunk counters (96 each)
__device__ int   g_ydone[Bb * N_CHUNKS];         // y chunk counters (16 each)

// bf16 hi/lo split buffers
__device__ __nv_bfloat16 g_xhi[(size_t)Bb * Ss * INs];
__device__ __nv_bfloat16 g_xlo[(size_t)Bb * Ss * INs];
__device__ __nv_bfloat16 g_whi[(size_t)CHs * INs];
__device__ __nv_bfloat16 g_wlo[(size_t)CHs * INs];
__device__ __nv_bfloat16 g_yhi[(size_t)Bb * Ss * STATEs];
__device__ __nv_bfloat16 g_ylo[(size_t)Bb * Ss * STATEs];
__device__ __nv_bfloat16 g_ohi[(size_t)OUTs * STATEs];
__device__ __nv_bfloat16 g_olo[(size_t)OUTs * STATEs];

// ---------------- math helpers ----------------
__device__ __forceinline__ float fast_tanh(float x) {
    float e = __expf(2.0f * x);
    return 1.0f - 2.0f / (e + 1.0f);
}
__device__ __forceinline__ float fast_sigmoid(float x) {
    return 1.0f / (1.0f + __expf(-x));
}

__device__ __forceinline__ uint32_t smem_to_u32(const void* p) {
    uint32_t a;
    asm("{ .reg .u64 t; cvta.to.shared.u64 t, %1; cvt.u32.u64 %0, t; }"
        : "=r"(a) : "l"(p));
    return a;
}
__device__ __forceinline__ void cpa16(uint32_t s, const void* g) {
    asm volatile("cp.async.cg.shared.global [%0], [%1], 16;\n"
                 :: "r"(s), "l"(g) : "memory");
}
__device__ __forceinline__ void cpa_commit() {
    asm volatile("cp.async.commit_group;\n" ::: "memory");
}
template <int N>
__device__ __forceinline__ void cpa_wait() {
    asm volatile("cp.async.wait_group %0;\n" :: "n"(N) : "memory");
}
__device__ __forceinline__ void ldsm_x4(uint32_t* r, uint32_t addr) {
    asm volatile("ldmatrix.sync.aligned.m8n8.x4.shared.b16 {%0,%1,%2,%3}, [%4];"
                 : "=r"(r[0]), "=r"(r[1]), "=r"(r[2]), "=r"(r[3]) : "r"(addr));
}
__device__ __forceinline__ void mma_bf16(float* c, const uint32_t* a, const uint32_t* b) {
    asm volatile(
        "mma.sync.aligned.m16n8k16.row.col.f32.bf16.bf16.f32 "
        "{%0,%1,%2,%3}, {%4,%5,%6,%7}, {%8,%9}, {%0,%1,%2,%3};"
        : "+f"(c[0]), "+f"(c[1]), "+f"(c[2]), "+f"(c[3])
        : "r"(a[0]), "r"(a[1]), "r"(a[2]), "r"(a[3]), "r"(b[0]), "r"(b[1]));
}

// packed f32x2 helpers (sm_100+ PTX, not 'a'-gated)
__device__ __forceinline__ unsigned long long pack2(float x, float y) {
    unsigned long long r;
    asm("mov.b64 %0, {%1, %2};" : "=l"(r) : "f"(x), "f"(y));
    return r;
}
#define FMA2(acc, a, b) \
    asm("fma.rn.f32x2 %0, %1, %2, %0;" : "+l"(acc) : "l"(a), "l"(b))
#define ADD2(r, a, b) \
    asm("add.rn.f32x2 %0, %1, %2;" : "=l"(r) : "l"(a), "l"(b))

// ---------------- combined preamble: all splits + flag reset, ONE launch ---
// Flat region partition: [0, nx4) -> x, [nx4, nx4+nw4) -> w_in, then w_out.
__device__ __forceinline__ void split4(const float* __restrict__ in, size_t i,
                                       __nv_bfloat16* __restrict__ hi,
                                       __nv_bfloat16* __restrict__ lo)
{
    float4 v = *(const float4*)(in + i);
    __nv_bfloat16 h0 = __float2bfloat16(v.x);
    __nv_bfloat16 h1 = __float2bfloat16(v.y);
    __nv_bfloat16 h2 = __float2bfloat16(v.z);
    __nv_bfloat16 h3 = __float2bfloat16(v.w);
    __nv_bfloat16 l0 = __float2bfloat16(v.x - __bfloat162float(h0));
    __nv_bfloat16 l1 = __float2bfloat16(v.y - __bfloat162float(h1));
    __nv_bfloat16 l2 = __float2bfloat16(v.z - __bfloat162float(h2));
    __nv_bfloat16 l3 = __float2bfloat16(v.w - __bfloat162float(h3));
    __nv_bfloat162* H = (__nv_bfloat162*)(hi + i);
    __nv_bfloat162* L = (__nv_bfloat162*)(lo + i);
    H[0] = __nv_bfloat162(h0, h1); H[1] = __nv_bfloat162(h2, h3);
    L[0] = __nv_bfloat162(l0, l1); L[1] = __nv_bfloat162(l2, l3);
}

#define NX4 ((size_t)Bb * Ss * INs / 4)      // 4,194,304
#define NW4 ((size_t)CHs * INs / 4)          // 3,145,728
#define NO4 ((size_t)OUTs * STATEs / 4)      // 1,048,576
#define PRE_THREADS ((NX4 + NW4 + NO4 + 255) / 256)   // blocks of 256

__global__ void __launch_bounds__(256)
preamble(const float* __restrict__ x, const float* __restrict__ w_in,
         const float* __restrict__ wout)
{
    size_t t = (size_t)blockIdx.x * 256 + threadIdx.x;
    if (blockIdx.x == 0 && threadIdx.x < 128) {
        int i = threadIdx.x;
        if (i < N_CHUNKS) g_done[i] = 0;
        if (i < Bb * N_CHUNKS) g_ydone[i] = 0;
    }
    if (t < NX4) {
        split4(x, t * 4, g_xhi, g_xlo);
    } else if (t < NX4 + NW4) {
        size_t i = (t - NX4) * 4;
        split4(w_in, i, g_whi, g_wlo);
    } else if (t < NX4 + NW4 + NO4) {
        size_t i = (t - NX4 - NW4) * 4;
        split4(wout, i, g_ohi, g_olo);
    }
}

// ---------------- GEMM tile geometry ----------------------------------------
#define LDPB 144                     // padded row length in bytes (64 bf16 + pad)
#define ARR_BYTES (128 * LDPB)       // 18432 (128 rows)
#define STG_BYTES (4 * ARR_BYTES)    // 73728 (Ahi,Alo,Bhi,Blo per stage)
#define FUSED_SMEM (2 * STG_BYTES)   // 147456 (2-stage)

// ============================================================================
// FUSED (exact R10): CTAs [0,32) = GRU scan (inline conv, publishes y chunks);
// CTAs [32,148) = workers: 3072 GEMM1 tiles (publish z chunks), then
// 1024 GEMM2 tiles gated on y chunks. One persistent launch.
// ============================================================================
__global__ void __launch_bounds__(256, 1)
fused_all(const __nv_bfloat16* __restrict__ Ahi, const __nv_bfloat16* __restrict__ Alo,
          const __nv_bfloat16* __restrict__ Bhi, const __nv_bfloat16* __restrict__ Blo,
          const float* __restrict__ bias, float* __restrict__ Z,
          const float* __restrict__ sw,
          const float* __restrict__ cw, const float* __restrict__ cb,
          __nv_bfloat16* __restrict__ yh, __nv_bfloat16* __restrict__ yl,
          const __nv_bfloat16* __restrict__ Ohi, const __nv_bfloat16* __restrict__ Olo,
          float* __restrict__ Out)
{
    extern __shared__ char smem[];
    __shared__ __align__(16) unsigned long long h_pair[128];
    __shared__ __align__(16) unsigned long long rh_pair[128];
    __shared__ float sf[128];
    __shared__ unsigned long long pr[4][64], pf[4][64], pc[4][64];

    const int tid = threadIdx.x;

    if (blockIdx.x >= N_SCAN_CTAS) {
        // ================= worker: GEMM1 tiles then GEMM2 tiles =============
        const uint32_t su = smem_to_u32(smem);
        const int wk   = blockIdx.x - N_SCAN_CTAS;
        const int wid  = tid >> 5;
        const int lane = tid & 31;
        const int warp_m = wid >> 2;    // 0..1
        const int warp_n = wid & 3;     // 0..3
        const int K = INs;              // 2048 for both GEMMs
        const int NCH = K >> 6;

        const uint32_t a_lane = (uint32_t)((lane & 15) * LDPB + (lane >> 4) * 16)
                              + (uint32_t)(warp_m * 64) * LDPB;
        const int g = lane >> 3;
        const uint32_t b_lane = (uint32_t)((((g >> 1) * 8) + (lane & 7)) * LDPB + (g & 1) * 16)
                              + (uint32_t)(warp_n * 32) * LDPB;

        const __nv_bfloat16 *tA0, *tA1, *tB0, *tB1;
        int bm, bn, chunk = 0;
        bool g1;

        for (int t = wk; t < N_TILES + N_TILES2; t += N_WORKERS) {
            if (t < N_TILES) {
                g1 = true;
                chunk = t / TILES_PER_CHUNK;
                const int sub  = t % TILES_PER_CHUNK;
                const int bsub = sub / (CHs / 128);
                const int ncol = sub % (CHs / 128);
                bm = bsub * Ss + chunk * CHUNK_S;
                bn = ncol << 7;
                tA0 = Ahi; tA1 = Alo; tB0 = Bhi; tB1 = Blo;
            } else {
                g1 = false;
                const int tt   = t - N_TILES;
                const int c    = tt >> 5;         // chunk-major ordering
                const int sub  = tt & 31;
                const int bsub = sub >> 4;
                const int ncol = sub & 15;
                bm = bsub * Ss + c * CHUNK_S;
                bn = ncol << 7;
                tA0 = yh; tA1 = yl; tB0 = Ohi; tB1 = Olo;
                if (tid == 0) {
                    volatile int* p = &g_ydone[bsub * N_CHUNKS + c];
                    while (*p < Hh) { __nanosleep(128); }
                }
                __syncthreads();
                __threadfence();
            }

            auto load_chunk = [&](int ci, int st) {
                uint32_t sb = su + (uint32_t)st * STG_BYTES;
                size_t kbase = (size_t)ci * 64;
#pragma unroll
                for (int u = 0; u < 4; u++) {
                    int s   = tid + u * 256;
                    int row = s >> 3;
                    int ks  = s & 7;
                    uint32_t so = (uint32_t)row * LDPB + (uint32_t)ks * 16;
                    size_t gA = (size_t)(bm + row) * K + kbase + ks * 8;
                    size_t gB = (size_t)(bn + row) * K + kbase + ks * 8;
                    cpa16(sb +                 so, tA0 + gA);
                    cpa16(sb + 1 * ARR_BYTES + so, tA1 + gA);
                    cpa16(sb + 2 * ARR_BYTES + so, tB0 + gB);
                    cpa16(sb + 3 * ARR_BYTES + so, tB1 + gB);
                }
                cpa_commit();
            };

            float acc[4][4][4];
#pragma unroll
            for (int i = 0; i < 4; i++)
#pragma unroll
                for (int j = 0; j < 4; j++)
#pragma unroll
                    for (int k = 0; k < 4; k++) acc[i][j][k] = 0.0f;

            load_chunk(0, 0);
            for (int i = 0; i < NCH; i++) {
                __syncthreads();
                if (i + 1 < NCH) load_chunk(i + 1, (i + 1) & 1);
                if (i + 1 < NCH) cpa_wait<1>(); else cpa_wait<0>();
                __syncthreads();

                uint32_t sb  = su + (uint32_t)(i & 1) * STG_BYTES;
                uint32_t ah  = sb + a_lane;
                uint32_t al  = sb + 1 * ARR_BYTES + a_lane;
                uint32_t bh  = sb + 2 * ARR_BYTES + b_lane;
                uint32_t bl  = sb + 3 * ARR_BYTES + b_lane;

#pragma unroll
                for (int ks = 0; ks < 4; ks++) {
                    uint32_t ko = (uint32_t)ks * 32;
                    uint32_t fa_h[4][4], fa_l[4][4];
                    uint32_t fb_h[4][2], fb_l[4][2];
#pragma unroll
                    for (int mi = 0; mi < 4; mi++) {
                        ldsm_x4(fa_h[mi], ah + (uint32_t)(mi * 16) * LDPB + ko);
                        ldsm_x4(fa_l[mi], al + (uint32_t)(mi * 16) * LDPB + ko);
                    }
#pragma unroll
                    for (int p = 0; p < 2; p++) {
                        uint32_t r[4];
                        ldsm_x4(r, bh + (uint32_t)(p * 16) * LDPB + ko);
                        fb_h[p * 2 + 0][0] = r[0]; fb_h[p * 2 + 0][1] = r[1];
                        fb_h[p * 2 + 1][0] = r[2]; fb_h[p * 2 + 1][1] = r[3];
                        ldsm_x4(r, bl + (uint32_t)(p * 16) * LDPB + ko);
                        fb_l[p * 2 + 0][0] = r[0]; fb_l[p * 2 + 0][1] = r[1];
                        fb_l[p * 2 + 1][0] = r[2]; fb_l[p * 2 + 1][1] = r[3];
                    }
#pragma unroll
                    for (int mi = 0; mi < 4; mi++)
#pragma unroll
                        for (int ni = 0; ni < 4; ni++) {
                            mma_bf16(acc[mi][ni], fa_h[mi], fb_h[ni]);
                            mma_bf16(acc[mi][ni], fa_h[mi], fb_l[ni]);
                            mma_bf16(acc[mi][ni], fa_l[mi], fb_h[ni]);
                        }
                }
            }

            const int gid = lane >> 2;
            const int tig = lane & 3;
            if (g1) {
#pragma unroll
                for (int mi = 0; mi < 4; mi++) {
                    int row0 = bm + warp_m * 64 + mi * 16 + gid;
#pragma unroll
                    for (int ni = 0; ni < 4; ni++) {
                        int col = bn + warp_n * 32 + ni * 8 + tig * 2;
                        float b0 = bias[col], b1 = bias[col + 1];
                        float v0 = fast_tanh(acc[mi][ni][0] + b0);
                        float v1 = fast_tanh(acc[mi][ni][1] + b1);
                        float v2 = fast_tanh(acc[mi][ni][2] + b0);
                        float v3 = fast_tanh(acc[mi][ni][3] + b1);
                        *(float2*)(Z + (size_t)row0 * CHs + col)       = make_float2(v0, v1);
                        *(float2*)(Z + (size_t)(row0 + 8) * CHs + col) = make_float2(v2, v3);
                    }
                }
                __threadfence();
                __syncthreads();
                if (tid == 0) atomicAdd(&g_done[chunk], 1);
            } else {
#pragma unroll
                for (int mi = 0; mi < 4; mi++) {
                    int row0 = bm + warp_m * 64 + mi * 16 + gid;
#pragma unroll
                    for (int ni = 0; ni < 4; ni++) {
                        int col = bn + warp_n * 32 + ni * 8 + tig * 2;
                        *(float2*)(Out + (size_t)row0 * OUTs + col)
                            = make_float2(acc[mi][ni][0], acc[mi][ni][1]);
                        *(float2*)(Out + (size_t)(row0 + 8) * OUTs + col)
                            = make_float2(acc[mi][ni][2], acc[mi][ni][3]);
                    }
                }
            }
        }
        return;
    }

    // ================= GRU scan (exact R10) + inline conv + y publication ==
    const int b   = blockIdx.x >> 4;
    const int hh  = blockIdx.x & 15;
    const int c2  = tid & 63;
    const int q   = tid >> 6;
    const int d0  = q << 5;

    const float* wc_g = sw + (size_t)(hh)      * Dd * Dd;  // cand
    const float* wf_g = sw + (size_t)(16 + hh) * Dd * Dd;  // forget
    const float* wr_g = sw + (size_t)(32 + hh) * Dd * Dd;  // reset

    unsigned long long wc[32], wf[32], wr[32];
#pragma unroll
    for (int j = 0; j < 32; j++) {
        float2 t;
        t = *(const float2*)(wc_g + (size_t)(d0 + j) * 128 + 2 * c2);
        wc[j] = pack2(t.x * FACTOR_, t.y * FACTOR_);
        t = *(const float2*)(wf_g + (size_t)(d0 + j) * 128 + 2 * c2);
        wf[j] = pack2(t.x * FACTOR_, t.y * FACTOR_);
        t = *(const float2*)(wr_g + (size_t)(d0 + j) * 128 + 2 * c2);
        wr[j] = pack2(t.x * FACTOR_, t.y * FACTOR_);
    }
    if (tid < 128) h_pair[tid] = 0ULL;

    const int col = hh * 128 + tid;
    const float* zb = Z + (size_t)b * Ss * CHs;
    __nv_bfloat16* yhb = yh + (size_t)b * Ss * STATEs + col;
    __nv_bfloat16* ylb = yl + (size_t)b * Ss * STATEs + col;
    const float* prf = (const float*)pr;
    const float* pff = (const float*)pf;
    const float* pcf = (const float*)pc;

    float cwi0=0,cwi1=0,cwi2=0,cwi3=0, cwf0=0,cwf1=0,cwf2=0,cwf3=0;
    float cwr0=0,cwr1=0,cwr2=0,cwr3=0, cbi=0, cbf=0, cbr=0;
    if (tid < 128) {
        const float4 wi  = *(const float4*)(cw + (size_t)col * 4);
        const float4 wfv = *(const float4*)(cw + (size_t)(2048 + col) * 4);
        const float4 wrv = *(const float4*)(cw + (size_t)(4096 + col) * 4);
        cwi0=wi.x; cwi1=wi.y; cwi2=wi.z; cwi3=wi.w;
        cwf0=wfv.x; cwf1=wfv.y; cwf2=wfv.z; cwf3=wfv.w;
        cwr0=wrv.x; cwr1=wrv.y; cwr2=wrv.z; cwr3=wrv.w;
        cbi = cb[col]; cbf = cb[2048 + col]; cbr = cb[4096 + col];
    }
    __syncthreads();

    {
        volatile int* p = &g_done[0];
        while (*p < TILES_PER_CHUNK) { __nanosleep(128); }
        __threadfence();
    }
    float xi0=0,xi1=0,xi2=0, xf0=0,xf1=0,xf2=0, xr0=0,xr1=0,xr2=0;
    float cur_i=0, cur_f=0, cur_r=0;
    if (tid < 128) {
        cur_i = zb[col];
        cur_f = zb[2048 + col];
        cur_r = zb[4096 + col];
    }
    float hcur = 0.f;

    for (int s = 0; s < Ss; s++) {
        float zci=0, zcf=0, zcr=0;
        if (tid < 128) {
            zci = (cwi0*xi0 + cwi1*xi1 + cwi2*xi2 + cwi3*cur_i + cbi) * FACTOR_;
            zcf = (cwf0*xf0 + cwf1*xf1 + cwf2*xf2 + cwf3*cur_f + cbf) * FACTOR_;
            zcr = (cwr0*xr0 + cwr1*xr1 + cwr2*xr2 + cwr3*cur_r + cbr) * FACTOR_;
        }

        if ((s & (CHUNK_S - 1)) == (CHUNK_S - 1) && s + 1 < Ss) {
            volatile int* p = &g_done[(s + 1) >> 7];
            while (*p < TILES_PER_CHUNK) { __nanosleep(128); }
            __threadfence();
        }

        float ni = 0.f, nf = 0.f, nr = 0.f;
        if (tid < 128 && s + 1 < Ss) {
            const float* zs = zb + (size_t)(s + 1) * CHs;
            ni = zs[col];
            nf = zs[2048 + col];
            nr = zs[4096 + col];
        }

        // phase 1: partial r/f over d in [d0, d0+32), 2 accums per gate
        unsigned long long ar0 = 0ULL, ar1 = 0ULL, af0 = 0ULL, af1 = 0ULL;
        {
            const ulonglong2* hp = (const ulonglong2*)(h_pair + d0);
#pragma unroll
            for (int j = 0; j < 16; j++) {
                ulonglong2 hv = hp[j];
                FMA2(ar0, hv.x, wr[2 * j]);
                FMA2(af0, hv.x, wf[2 * j]);
                FMA2(ar1, hv.y, wr[2 * j + 1]);
                FMA2(af1, hv.y, wf[2 * j + 1]);
            }
        }
        unsigned long long art, aft;
        ADD2(art, ar0, ar1);
        ADD2(aft, af0, af1);
        pr[q][c2] = art;
        pf[q][c2] = aft;
        __syncthreads();

        float ff = 0.f;
        if (tid < 128) {
            float rs = zcr + prf[tid] + prf[128 + tid] + prf[256 + tid] + prf[384 + tid];
            float fs = zcf + pff[tid] + pff[128 + tid] + pff[256 + tid] + pff[384 + tid];
            float r  = fast_sigmoid(rs);
            ff = fast_sigmoid(fs);
            float rh = r * hcur;
            rh_pair[tid] = pack2(rh, rh);
            sf[tid] = ff;
        }
        __syncthreads();

        // phase 2: partial cand on (r*h)
        unsigned long long ac0 = 0ULL, ac1 = 0ULL;
        {
            const ulonglong2* rp = (const ulonglong2*)(rh_pair + d0);
#pragma unroll
            for (int j = 0; j < 16; j++) {
                ulonglong2 hv = rp[j];
                FMA2(ac0, hv.x, wc[2 * j]);
                FMA2(ac1, hv.y, wc[2 * j + 1]);
            }
        }
        unsigned long long act;
        ADD2(act, ac0, ac1);
        pc[q][c2] = act;
        __syncthreads();

        if (tid < 128) {
            float cs = zci + pcf[tid] + pcf[128 + tid] + pcf[256 + tid] + pcf[384 + tid];
            float cd = fast_tanh(cs);
            float hn = fmaf(ff, hcur - cd, cd);
            hcur = hn;
            h_pair[tid] = pack2(hn, hn);
            __nv_bfloat16 bh = __float2bfloat16(hn);
            yhb[(size_t)s * STATEs] = bh;
            ylb[(size_t)s * STATEs] = __float2bfloat16(hn - __bfloat162float(bh));
            xi0 = xi1; xi1 = xi2; xi2 = cur_i; cur_i = ni;
            xf0 = xf1; xf1 = xf2; xf2 = cur_f; cur_f = nf;
            xr0 = xr1; xr1 = xr2; xr2 = cur_r; cur_r = nr;
        }
        __syncthreads();

        if ((s & (CHUNK_S - 1)) == (CHUNK_S - 1)) {
            __threadfence();
            __syncthreads();
            if (tid == 0) atomicAdd(&g_ydone[b * N_CHUNKS + (s >> 7)], 1);
        }
    }
}

// ---------------- launch ----------------
extern "C" void kernel_launch(void* const* d_in, const int* in_sizes, int n_in,
                              void* d_out, int out_size)
{
    const float* x    = (const float*)d_in[0];
    const float* w_in = (const float*)d_in[1];
    const float* b_in = (const float*)d_in[2];
    const float* cw   = (const float*)d_in[3];
    const float* cb   = (const float*)d_in[4];
    const float* swt  = (const float*)d_in[5];
    const float* wout = (const float*)d_in[6];
    float* out = (float*)d_out;

    float* zp;
    cudaGetSymbolAddress((void**)&zp, g_z);
    __nv_bfloat16 *xh, *xl, *wh, *wl, *yh, *yl, *oh, *ol;
    cudaGetSymbolAddress((void**)&xh, g_xhi);
    cudaGetSymbolAddress((void**)&xl, g_xlo);
    cudaGetSymbolAddress((void**)&wh, g_whi);
    cudaGetSymbolAddress((void**)&wl, g_wlo);
    cudaGetSymbolAddress((void**)&yh, g_yhi);
    cudaGetSymbolAddress((void**)&yl, g_ylo);
    cudaGetSymbolAddress((void**)&oh, g_ohi);
    cudaGetSymbolAddress((void**)&ol, g_olo);

    // ONE preamble launch: all hi/lo splits + flag reset
    {
        int blocks = (int)PRE_THREADS;
        preamble<<<blocks, 256>>>(x, w_in, wout);
    }

    // fused GEMM1 + conv + scan + GEMM2
    {
        cudaFuncSetAttribute(fused_all,
                             cudaFuncAttributeMaxDynamicSharedMemorySize,
                             FUSED_SMEM);
        fused_all<<<N_SCAN_CTAS + N_WORKERS, 256, FUSED_SMEM>>>(
            xh, xl, wh, wl, b_in, zp, swt, cw, cb, yh, yl, oh, ol, out);
    }
}